// round 2
// baseline (speedup 1.0000x reference)
#include <cuda_runtime.h>
#include <cstdint>

#define NIMG  4
#define CCH   80
#define TOPN  500
#define NCAND 1500
#define NBINS (1<<18)
#define CAP0 524288
#define CAP1 131072
#define CAP2 65536
#define CAPI (CAP0+CAP1+CAP2)
#define BOX_LOGIT_THRESH (-2.9444389791664403f)

__device__ unsigned long long g_cand[NIMG * CAPI];
__device__ unsigned int       g_hist[NIMG * 3 * NBINS];
__device__ unsigned int       g_cnt[NIMG * 3];
__device__ unsigned long long g_top[NIMG * NCAND];
__device__ float g_x1[NIMG*NCAND], g_y1[NIMG*NCAND], g_x2[NIMG*NCAND], g_y2[NIMG*NCAND];
__device__ int   g_lb[NIMG*NCAND];
__device__ unsigned char g_vd[NIMG*NCAND];

__constant__ int c_cap[3]  = {CAP0, CAP1, CAP2};
__constant__ int c_loff[3] = {0, CAP0, CAP0 + CAP1};

__device__ __forceinline__ float sigm(float x) {
    if (x >= 0.f) return 1.f / (1.f + expf(-x));
    float e = expf(x); return e / (1.f + e);
}

__device__ void bitonic_desc(unsigned long long* a, int sz) {
    for (int k = 2; k <= sz; k <<= 1)
        for (int j = k >> 1; j > 0; j >>= 1) {
            for (int t = threadIdx.x; t < sz; t += blockDim.x) {
                int ixj = t ^ j;
                if (ixj > t) {
                    unsigned long long u = a[t], v = a[ixj];
                    bool sw = ((t & k) == 0) ? (u < v) : (u > v);
                    if (sw) { a[t] = v; a[ixj] = u; }
                }
            }
            __syncthreads();
        }
}

__global__ void k_zero() {
    int tid = blockIdx.x * blockDim.x + threadIdx.x;
    int st = gridDim.x * blockDim.x;
    for (int i = tid; i < NIMG * 3 * NBINS; i += st) g_hist[i] = 0;
    if (tid < NIMG * 3) g_cnt[tid] = 0;
}

__global__ void k_score(const float* __restrict__ cls, const float* __restrict__ gau,
                        int H, int W, int lvl, int capL, int loff) {
    int hw = H * W, CHW = CCH * hw;
    int idx = blockIdx.x * blockDim.x + threadIdx.x;
    if (idx >= NIMG * CHW) return;
    int n = idx / CHW;
    int r = idx - n * CHW;
    int pp = r % hw;
    int y = pp / W, x = pp - y * W;
    if (y == 0 || x == 0 || y == H - 1 || x == W - 1) return;
    float cl = cls[idx];
    if (!(cl > BOX_LOGIT_THRESH)) return;
    const float* G = gau + (idx - pp);
    int o = pp;
    float gc = G[o];
    float m = G[o-W-1];
    m = fmaxf(m, G[o-W]);   m = fmaxf(m, G[o-W+1]);
    m = fmaxf(m, G[o-1]);   m = fmaxf(m, G[o+1]);
    m = fmaxf(m, G[o+W-1]); m = fmaxf(m, G[o+W]); m = fmaxf(m, G[o+W+1]);
    if (!(gc >= m)) return;
    float sc = sqrtf(sigm(cl) * sigm(gc));
    unsigned sb = __float_as_uint(sc);
    int b = n * 3 + lvl;
    atomicAdd(&g_hist[(size_t)b * NBINS + (sb >> 12)], 1u);
    unsigned slot = atomicAdd(&g_cnt[b], 1u);
    if (slot < (unsigned)capL)
        g_cand[(size_t)n * CAPI + loff + slot] =
            ((unsigned long long)sb << 32) | (unsigned)(~r);
}

__global__ void __launch_bounds__(1024) k_select() {
    int b = blockIdx.x;
    int n = b / 3, lvl = b % 3;
    const unsigned int* hist = &g_hist[(size_t)b * NBINS];
    __shared__ unsigned int cs[1024];
    __shared__ unsigned long long sel[4096];
    __shared__ unsigned int sT, sM;
    int tid = threadIdx.x;
    unsigned s = 0;
    int base = tid * 256;
    #pragma unroll 8
    for (int i = 0; i < 256; i++) s += hist[base + i];
    cs[tid] = s;
    if (tid == 0) sM = 0;
    __syncthreads();
    if (tid == 0) {
        unsigned acc = 0; int tc = -1;
        for (int t = 1023; t >= 0; --t) { acc += cs[t]; if (acc >= TOPN) { tc = t; break; } }
        unsigned T = 0;
        if (tc >= 0) {
            unsigned acc2 = acc - cs[tc];
            for (int bb = tc * 256 + 255; bb >= tc * 256; --bb) {
                acc2 += hist[bb];
                if (acc2 >= TOPN) { T = (unsigned)bb; break; }
            }
        }
        sT = T;
    }
    __syncthreads();
    unsigned T = sT;
    unsigned cnt = min(g_cnt[b], (unsigned)c_cap[lvl]);
    const unsigned long long* cand = &g_cand[(size_t)n * CAPI + c_loff[lvl]];
    for (unsigned i = tid; i < cnt; i += blockDim.x) {
        unsigned long long k = cand[i];
        if ((unsigned)(k >> 44) >= T) {
            unsigned p = atomicAdd(&sM, 1u);
            if (p < 4096) sel[p] = k;
        }
    }
    __syncthreads();
    unsigned mM = min(sM, 4096u);
    for (int i = tid; i < 4096; i += blockDim.x)
        if ((unsigned)i >= mM) sel[i] = 0ull;
    __syncthreads();
    bitonic_desc(sel, 4096);
    if (tid < TOPN)
        g_top[(size_t)n * NCAND + lvl * TOPN + tid] = sel[tid];
}

__global__ void k_solve(const float* __restrict__ g0, const float* __restrict__ g1,
                        const float* __restrict__ g2) {
    int t = blockIdx.x * blockDim.x + threadIdx.x;
    if (t >= NIMG * NCAND) return;
    int n = t / NCAND, p = t - n * NCAND;
    int lvl = p / TOPN;
    int H, W, step; const float* G;
    if (lvl == 0)      { H = 160; W = 256; step = 8;  G = g0; }
    else if (lvl == 1) { H = 80;  W = 128; step = 16; G = g1; }
    else               { H = 40;  W = 64;  step = 32; G = g2; }
    unsigned long long key = g_top[t];
    float sc = __uint_as_float((unsigned)(key >> 32));
    unsigned flat = ~(unsigned)key;
    int hw = H * W;
    if (!(sc > 0.f) || flat >= (unsigned)(CCH * hw)) {
        g_x1[t]=0.f; g_y1[t]=0.f; g_x2[t]=0.f; g_y2[t]=0.f; g_lb[t]=1; g_vd[t]=0;
        return;
    }
    int c = (int)(flat / hw);
    int rem = (int)(flat - (unsigned)c * hw);
    int y = rem / W, x = rem - y * W;
    const float* B = G + ((size_t)(n * CCH + c)) * hw;
    auto LV = [&](int yy, int xx) -> float {
        yy = min(max(yy, 0), H - 1);
        xx = min(max(xx, 0), W - 1);
        return log1pf(expf(-B[yy * W + xx])) * 0.125f;
    };
    float l0 = LV(y, x);
    float lxp = LV(y, x+1), lxm = LV(y, x-1);
    float lyp = LV(y+1, x), lym = LV(y-1, x);
    float Ax = (lxp + lxm - 2.f * l0) * 0.5f;
    float Ay = (lyp + lym - 2.f * l0) * 0.5f;
    bool px = Ax > 1e-8f, py = Ay > 1e-8f;
    float Axs = px ? Ax : 1.f, Ays = py ? Ay : 1.f;
    float mux = (float)x - (lxp - lxm) / (4.f * Axs);
    float muy = (float)y - (lyp - lym) / (4.f * Ays);
    float wb = (px ? rsqrtf(2.f * Axs) : 0.f) * (float)step;
    float hb = (py ? rsqrtf(2.f * Ays) : 0.f) * (float)step;
    float x1 = mux * (float)step - 0.5f * wb + (float)(step - 1) * 0.5f;
    float y1 = muy * (float)step - 0.5f * hb + (float)(step - 1) * 0.5f;
    bool vd = (wb > 0.f) && (hb > 0.f);
    float x2 = x1 + wb - 1.f, y2 = y1 + hb - 1.f;
    g_x1[t] = fminf(fmaxf(x1, 0.f), 2047.f);
    g_x2[t] = fminf(fmaxf(x2, 0.f), 2047.f);
    g_y1[t] = fminf(fmaxf(y1, 0.f), 1279.f);
    g_y2[t] = fminf(fmaxf(y2, 0.f), 1279.f);
    g_lb[t] = c + 1; g_vd[t] = vd ? 1 : 0;
}

__global__ void __launch_bounds__(1024) k_nms(float* __restrict__ out) {
    __shared__ unsigned long long skey[2048];
    __shared__ float bx1[NCAND], by1[NCAND], bx2[NCAND], by2[NCAND];
    __shared__ short slb[NCAND];
    __shared__ unsigned char keep[NCAND];
    __shared__ int s_ti[100];
    __shared__ unsigned int s_cm;
    int n = blockIdx.x, tid = threadIdx.x;

    for (int p = tid; p < 2048; p += 1024) {
        unsigned long long kk = 0ull;
        if (p < NCAND) {
            int gi = n * NCAND + p;
            float sc = __uint_as_float((unsigned)(g_top[gi] >> 32));
            float sv = g_vd[gi] ? sc : -1.f;
            unsigned bits = __float_as_uint(sv);
            unsigned ord = (bits & 0x80000000u) ? ~bits : (bits | 0x80000000u);
            kk = ((unsigned long long)ord << 32) | (0xFFFFFFFFu - (unsigned)p);
        }
        skey[p] = kk;
    }
    __syncthreads();
    bitonic_desc(skey, 2048);

    for (int p = tid; p < NCAND; p += 1024) {
        int pos = (int)(0xFFFFFFFFu - (unsigned)skey[p]);
        int gi = n * NCAND + pos;
        bx1[p]=g_x1[gi]; by1[p]=g_y1[gi]; bx2[p]=g_x2[gi]; by2[p]=g_y2[gi];
        slb[p]=(short)g_lb[gi]; keep[p]=g_vd[gi];
    }
    __syncthreads();

    for (int cb = 0; cb < NCAND; cb += 32) {
        if (tid < 32) {
            int l = tid, i = cb + l;
            bool in = i < NCAND;
            float ax1=0,ay1=0,ax2=0,ay2=0,aar=0;
            int alab = -1; bool alive = false;
            if (in) {
                ax1=bx1[i]; ay1=by1[i]; ax2=bx2[i]; ay2=by2[i];
                aar=(ax2-ax1+1.f)*(ay2-ay1+1.f);
                alab=slb[i]; alive=keep[i]!=0;
            }
            unsigned sup = 0;
            #pragma unroll 1
            for (int m = 0; m < 31; m++) {
                float mx1=__shfl_sync(~0u,ax1,m), my1=__shfl_sync(~0u,ay1,m);
                float mx2=__shfl_sync(~0u,ax2,m), my2=__shfl_sync(~0u,ay2,m);
                float mar=__shfl_sync(~0u,aar,m);
                int mlb=__shfl_sync(~0u,alab,m);
                if (m < l) {
                    float iw=fmaxf(fminf(ax2,mx2)-fmaxf(ax1,mx1)+1.f,0.f);
                    float ih=fmaxf(fminf(ay2,my2)-fmaxf(ay1,my1)+1.f,0.f);
                    float inter=iw*ih;
                    float iou=inter/(aar+mar-inter+1e-9f);
                    if (iou > 0.5f && alab == mlb) sup |= (1u << m);
                }
            }
            #pragma unroll 1
            for (int b2 = 0; b2 < 31; b2++) {
                int kb = __shfl_sync(~0u, (int)alive, b2);
                if (b2 < l && kb && ((sup >> b2) & 1u)) alive = false;
            }
            if (in) keep[i] = alive ? 1 : 0;
            unsigned cm = __ballot_sync(~0u, alive && in);
            if (l == 0) s_cm = cm;
        }
        __syncthreads();
        unsigned cm = s_cm;
        if (cm) {
            for (int j = cb + 32 + tid; j < NCAND; j += 1024) {
                if (!keep[j]) continue;
                float jx1=bx1[j],jy1=by1[j],jx2=bx2[j],jy2=by2[j];
                float jar=(jx2-jx1+1.f)*(jy2-jy1+1.f);
                short jlb=slb[j];
                unsigned mm = cm;
                bool dead = false;
                while (mm) {
                    int b2 = __ffs(mm) - 1; mm &= mm - 1;
                    int i = cb + b2;
                    if (slb[i] != jlb) continue;
                    float ix1=bx1[i],iy1=by1[i],ix2=bx2[i],iy2=by2[i];
                    float iw=fmaxf(fminf(jx2,ix2)-fmaxf(jx1,ix1)+1.f,0.f);
                    float ih=fmaxf(fminf(jy2,iy2)-fmaxf(jy1,iy1)+1.f,0.f);
                    float inter=iw*ih;
                    float iar=(ix2-ix1+1.f)*(iy2-iy1+1.f);
                    if (inter/(jar+iar-inter+1e-9f) > 0.5f) { dead = true; break; }
                }
                if (dead) keep[j] = 0;
            }
        }
        __syncthreads();
    }

    if (tid < 32) {
        int lane = tid, cnt = 0;
        for (int pass = 0; pass < 2; pass++) {
            for (int b2 = 0; b2 < NCAND && cnt < 100; b2 += 32) {
                int i = b2 + lane;
                bool pr = (i < NCAND) && ((pass == 0) ? (keep[i] != 0) : (keep[i] == 0));
                unsigned w = __ballot_sync(~0u, pr);
                int pre = __popc(w & ((1u << lane) - 1u));
                if (pr && cnt + pre < 100) s_ti[cnt + pre] = i;
                cnt += __popc(w);
            }
            if (cnt > 100) cnt = 100;
        }
    }
    __syncthreads();

    if (tid < 100) {
        int p = s_ti[tid];
        unsigned ord = (unsigned)(skey[p] >> 32);
        float s = (ord & 0x80000000u) ? __uint_as_float(ord ^ 0x80000000u)
                                      : __uint_as_float(~ord);
        float tv = keep[p] ? s : -1.f;
        out[n*400 + tid*4 + 0] = bx1[p];
        out[n*400 + tid*4 + 1] = by1[p];
        out[n*400 + tid*4 + 2] = bx2[p];
        out[n*400 + tid*4 + 3] = by2[p];
        out[1600 + n*100 + tid] = tv;
        out[2000 + n*100 + tid] = (float)slb[p];
        out[2400 + n*100 + tid] = (tv > 0.f) ? 1.f : 0.f;
    }
}

extern "C" void kernel_launch(void* const* d_in, const int* in_sizes, int n_in,
                              void* d_out, int out_size) {
    // Resolve input ordering: grouped (cls0,cls1,cls2,gau0,gau1,gau2) vs
    // interleaved (cls0,gau0,cls1,gau1,cls2,gau2) — level sizes differ 4x.
    const float *cls[3], *gau[3];
    if (in_sizes[0] == in_sizes[1]) {          // interleaved
        cls[0]=(const float*)d_in[0]; gau[0]=(const float*)d_in[1];
        cls[1]=(const float*)d_in[2]; gau[1]=(const float*)d_in[3];
        cls[2]=(const float*)d_in[4]; gau[2]=(const float*)d_in[5];
    } else {                                   // grouped
        cls[0]=(const float*)d_in[0]; cls[1]=(const float*)d_in[1]; cls[2]=(const float*)d_in[2];
        gau[0]=(const float*)d_in[3]; gau[1]=(const float*)d_in[4]; gau[2]=(const float*)d_in[5];
    }
    float* out = (float*)d_out;

    k_zero<<<2048, 256>>>();

    const int Hs[3]={160,80,40}, Ws[3]={256,128,64};
    for (int l = 0; l < 3; l++) {
        int tot = NIMG * CCH * Hs[l] * Ws[l];
        int caps[3] = {CAP0, CAP1, CAP2};
        int loffs[3] = {0, CAP0, CAP0 + CAP1};
        k_score<<<(tot + 255) / 256, 256>>>(cls[l], gau[l], Hs[l], Ws[l], l, caps[l], loffs[l]);
    }
    k_select<<<NIMG * 3, 1024>>>();
    k_solve<<<(NIMG * NCAND + 255) / 256, 256>>>(gau[0], gau[1], gau[2]);
    k_nms<<<NIMG, 1024>>>(out);
}

// round 4
// speedup vs baseline: 1.1926x; 1.1926x over previous
#include <cuda_runtime.h>
#include <cstdint>

#define NIMG  4
#define CCH   80
#define TOPN  500
#define NCAND 1500
#define NBINS (1<<18)
#define CAP0 524288
#define CAP1 131072
#define CAP2 65536
#define CAPI (CAP0+CAP1+CAP2)
#define BOX_LOGIT_THRESH (-2.9444389791664403f)

__device__ unsigned long long g_cand[NIMG * CAPI];
__device__ unsigned int       g_hist[NIMG * 3 * NBINS];
__device__ unsigned int       g_cnt[NIMG * 3];
__device__ unsigned long long g_top[NIMG * NCAND];
__device__ float g_x1[NIMG*NCAND], g_y1[NIMG*NCAND], g_x2[NIMG*NCAND], g_y2[NIMG*NCAND];
__device__ int   g_lb[NIMG*NCAND];
__device__ unsigned char g_vd[NIMG*NCAND];

__constant__ int c_cap[3]  = {CAP0, CAP1, CAP2};
__constant__ int c_loff[3] = {0, CAP0, CAP0 + CAP1};

__device__ __forceinline__ float sigm(float x) {
    if (x >= 0.f) return 1.f / (1.f + expf(-x));
    float e = expf(x); return e / (1.f + e);
}

__device__ void bitonic_desc(unsigned long long* a, int sz) {
    for (int k = 2; k <= sz; k <<= 1)
        for (int j = k >> 1; j > 0; j >>= 1) {
            for (int t = threadIdx.x; t < sz; t += blockDim.x) {
                int ixj = t ^ j;
                if (ixj > t) {
                    unsigned long long u = a[t], v = a[ixj];
                    bool sw = ((t & k) == 0) ? (u < v) : (u > v);
                    if (sw) { a[t] = v; a[ixj] = u; }
                }
            }
            __syncthreads();
        }
}

__global__ void k_zero() {
    int tid = blockIdx.x * blockDim.x + threadIdx.x;
    int st = gridDim.x * blockDim.x;
    uint4* h4 = (uint4*)g_hist;
    for (int i = tid; i < (NIMG * 3 * NBINS) / 4; i += st)
        h4[i] = make_uint4(0u, 0u, 0u, 0u);
    if (tid < NIMG * 3) g_cnt[tid] = 0;
}

// warp-aggregated candidate emit: (n,lvl) is warp-uniform since CHW % 256 == 0
__global__ void k_score(const float* __restrict__ cls, const float* __restrict__ gau,
                        int H, int W, int lvl, int capL, int loff) {
    int hw = H * W, CHW = CCH * hw;
    int idx = blockIdx.x * blockDim.x + threadIdx.x;
    int n = idx / CHW;
    int r = idx - n * CHW;
    int pp = r % hw;
    int y = pp / W, x = pp - y * W;

    bool cand = false;
    unsigned sb = 0;
    if (!(y == 0 || x == 0 || y == H - 1 || x == W - 1)) {
        float cl = cls[idx];
        if (cl > BOX_LOGIT_THRESH) {
            const float* G = gau + (idx - pp);
            int o = pp;
            float gc = G[o];
            float m = G[o-W-1];
            m = fmaxf(m, G[o-W]);   m = fmaxf(m, G[o-W+1]);
            m = fmaxf(m, G[o-1]);   m = fmaxf(m, G[o+1]);
            m = fmaxf(m, G[o+W-1]); m = fmaxf(m, G[o+W]); m = fmaxf(m, G[o+W+1]);
            if (gc >= m) {
                float sc = sqrtf(sigm(cl) * sigm(gc));
                sb = __float_as_uint(sc);
                cand = true;
            }
        }
    }

    unsigned ball = __ballot_sync(0xFFFFFFFFu, cand);
    if (ball == 0u) return;
    int b = n * 3 + lvl;                     // warp-uniform
    int lane = threadIdx.x & 31;
    int lead = __ffs(ball) - 1;
    unsigned base = 0;
    if (lane == lead) base = atomicAdd(&g_cnt[b], (unsigned)__popc(ball));
    base = __shfl_sync(0xFFFFFFFFu, base, lead);
    if (cand) {
        atomicAdd(&g_hist[(size_t)b * NBINS + (sb >> 12)], 1u);
        unsigned slot = base + (unsigned)__popc(ball & ((1u << lane) - 1u));
        if (slot < (unsigned)capL)
            g_cand[(size_t)n * CAPI + loff + slot] =
                ((unsigned long long)sb << 32) | (unsigned)(~r);
    }
}

__global__ void __launch_bounds__(1024) k_select() {
    int b = blockIdx.x;
    int n = b / 3, lvl = b % 3;
    const unsigned int* hist = &g_hist[(size_t)b * NBINS];
    __shared__ unsigned int cs[1024];
    __shared__ unsigned int fine[256];
    __shared__ unsigned long long sel[4096];
    __shared__ unsigned int sT, sM;
    __shared__ int s_tc;
    int tid = threadIdx.x;

    const uint4* h4 = (const uint4*)hist;
    unsigned s = 0;
    int b4 = tid * 64;
    #pragma unroll 16
    for (int i = 0; i < 64; i++) {
        uint4 v = h4[b4 + i];
        s += v.x + v.y + v.z + v.w;
    }
    cs[tid] = s;
    if (tid == 0) sM = 0;
    __syncthreads();

    if (tid == 0) {
        unsigned acc = 0; int tc = -1;
        for (int t = 1023; t >= 0; --t) { acc += cs[t]; if (acc >= TOPN) { tc = t; break; } }
        s_tc = tc;
        cs[1023] = (tc >= 0) ? (acc - cs[tc]) : 0;
    }
    __syncthreads();
    int tc = s_tc;
    if (tc >= 0 && tid < 256) fine[tid] = hist[tc * 256 + tid];
    __syncthreads();
    if (tid == 0) {
        unsigned T = 0;
        if (tc >= 0) {
            unsigned acc2 = cs[1023];
            for (int bb = 255; bb >= 0; --bb) {
                acc2 += fine[bb];
                if (acc2 >= TOPN) { T = (unsigned)(tc * 256 + bb); break; }
            }
        }
        sT = T;
    }
    __syncthreads();
    unsigned T = sT;

    unsigned cnt = min(g_cnt[b], (unsigned)c_cap[lvl]);
    const unsigned long long* cand = &g_cand[(size_t)n * CAPI + c_loff[lvl]];
    for (unsigned i = tid; i < cnt; i += blockDim.x) {
        unsigned long long k = cand[i];
        if ((unsigned)(k >> 44) >= T) {
            unsigned p = atomicAdd(&sM, 1u);
            if (p < 4096) sel[p] = k;
        }
    }
    __syncthreads();
    unsigned mM = min(sM, 4096u);
    for (int i = tid; i < 4096; i += blockDim.x)
        if ((unsigned)i >= mM) sel[i] = 0ull;
    __syncthreads();
    bitonic_desc(sel, 4096);
    if (tid < TOPN)
        g_top[(size_t)n * NCAND + lvl * TOPN + tid] = sel[tid];
}

__global__ void k_solve(const float* __restrict__ g0, const float* __restrict__ g1,
                        const float* __restrict__ g2) {
    int t = blockIdx.x * blockDim.x + threadIdx.x;
    if (t >= NIMG * NCAND) return;
    int n = t / NCAND, p = t - n * NCAND;
    int lvl = p / TOPN;
    int H, W, step; const float* G;
    if (lvl == 0)      { H = 160; W = 256; step = 8;  G = g0; }
    else if (lvl == 1) { H = 80;  W = 128; step = 16; G = g1; }
    else               { H = 40;  W = 64;  step = 32; G = g2; }
    unsigned long long key = g_top[t];
    float sc = __uint_as_float((unsigned)(key >> 32));
    unsigned flat = ~(unsigned)key;
    int hw = H * W;
    if (!(sc > 0.f) || flat >= (unsigned)(CCH * hw)) {
        g_x1[t]=0.f; g_y1[t]=0.f; g_x2[t]=0.f; g_y2[t]=0.f; g_lb[t]=1; g_vd[t]=0;
        return;
    }
    int c = (int)(flat / hw);
    int rem = (int)(flat - (unsigned)c * hw);
    int y = rem / W, x = rem - y * W;
    const float* B = G + ((size_t)(n * CCH + c)) * hw;
    auto LV = [&](int yy, int xx) -> float {
        yy = min(max(yy, 0), H - 1);
        xx = min(max(xx, 0), W - 1);
        return log1pf(expf(-B[yy * W + xx])) * 0.125f;
    };
    float l0 = LV(y, x);
    float lxp = LV(y, x+1), lxm = LV(y, x-1);
    float lyp = LV(y+1, x), lym = LV(y-1, x);
    float Ax = (lxp + lxm - 2.f * l0) * 0.5f;
    float Ay = (lyp + lym - 2.f * l0) * 0.5f;
    bool px = Ax > 1e-8f, py = Ay > 1e-8f;
    float Axs = px ? Ax : 1.f, Ays = py ? Ay : 1.f;
    float mux = (float)x - (lxp - lxm) / (4.f * Axs);
    float muy = (float)y - (lyp - lym) / (4.f * Ays);
    float wb = (px ? rsqrtf(2.f * Axs) : 0.f) * (float)step;
    float hb = (py ? rsqrtf(2.f * Ays) : 0.f) * (float)step;
    float x1 = mux * (float)step - 0.5f * wb + (float)(step - 1) * 0.5f;
    float y1 = muy * (float)step - 0.5f * hb + (float)(step - 1) * 0.5f;
    bool vd = (wb > 0.f) && (hb > 0.f);
    float x2 = x1 + wb - 1.f, y2 = y1 + hb - 1.f;
    g_x1[t] = fminf(fmaxf(x1, 0.f), 2047.f);
    g_x2[t] = fminf(fmaxf(x2, 0.f), 2047.f);
    g_y1[t] = fminf(fmaxf(y1, 0.f), 1279.f);
    g_y2[t] = fminf(fmaxf(y2, 0.f), 1279.f);
    g_lb[t] = c + 1; g_vd[t] = vd ? 1 : 0;
}

__global__ void __launch_bounds__(1024) k_nms(float* __restrict__ out) {
    __shared__ unsigned long long skey[2048];
    __shared__ float bx1[NCAND], by1[NCAND], bx2[NCAND], by2[NCAND];
    __shared__ short slb[NCAND];
    __shared__ unsigned char keep[NCAND];
    __shared__ int s_ti[100];
    __shared__ unsigned int s_cm;
    int n = blockIdx.x, tid = threadIdx.x;

    for (int p = tid; p < 2048; p += 1024) {
        unsigned long long kk = 0ull;
        if (p < NCAND) {
            int gi = n * NCAND + p;
            float sc = __uint_as_float((unsigned)(g_top[gi] >> 32));
            float sv = g_vd[gi] ? sc : -1.f;
            unsigned bits = __float_as_uint(sv);
            unsigned ord = (bits & 0x80000000u) ? ~bits : (bits | 0x80000000u);
            kk = ((unsigned long long)ord << 32) | (0xFFFFFFFFu - (unsigned)p);
        }
        skey[p] = kk;
    }
    __syncthreads();
    bitonic_desc(skey, 2048);

    for (int p = tid; p < NCAND; p += 1024) {
        int pos = (int)(0xFFFFFFFFu - (unsigned)skey[p]);
        int gi = n * NCAND + pos;
        bx1[p]=g_x1[gi]; by1[p]=g_y1[gi]; bx2[p]=g_x2[gi]; by2[p]=g_y2[gi];
        slb[p]=(short)g_lb[gi]; keep[p]=g_vd[gi];
    }
    __syncthreads();

    for (int cb = 0; cb < NCAND; cb += 32) {
        if (tid < 32) {
            int l = tid, i = cb + l;
            bool in = i < NCAND;
            float ax1=0,ay1=0,ax2=0,ay2=0,aar=0;
            int alab = -1; bool alive = false;
            if (in) {
                ax1=bx1[i]; ay1=by1[i]; ax2=bx2[i]; ay2=by2[i];
                aar=(ax2-ax1+1.f)*(ay2-ay1+1.f);
                alab=slb[i]; alive=keep[i]!=0;
            }
            unsigned sup = 0;
            #pragma unroll 1
            for (int m = 0; m < 31; m++) {
                float mx1=__shfl_sync(~0u,ax1,m), my1=__shfl_sync(~0u,ay1,m);
                float mx2=__shfl_sync(~0u,ax2,m), my2=__shfl_sync(~0u,ay2,m);
                float mar=__shfl_sync(~0u,aar,m);
                int mlb=__shfl_sync(~0u,alab,m);
                if (m < l) {
                    float iw=fmaxf(fminf(ax2,mx2)-fmaxf(ax1,mx1)+1.f,0.f);
                    float ih=fmaxf(fminf(ay2,my2)-fmaxf(ay1,my1)+1.f,0.f);
                    float inter=iw*ih;
                    float iou=inter/(aar+mar-inter+1e-9f);
                    if (iou > 0.5f && alab == mlb) sup |= (1u << m);
                }
            }
            #pragma unroll 1
            for (int b2 = 0; b2 < 31; b2++) {
                int kb = __shfl_sync(~0u, (int)alive, b2);
                if (b2 < l && kb && ((sup >> b2) & 1u)) alive = false;
            }
            if (in) keep[i] = alive ? 1 : 0;
            unsigned cm = __ballot_sync(~0u, alive && in);
            if (l == 0) s_cm = cm;
        }
        __syncthreads();
        unsigned cm = s_cm;
        if (cm) {
            for (int j = cb + 32 + tid; j < NCAND; j += 1024) {
                if (!keep[j]) continue;
                float jx1=bx1[j],jy1=by1[j],jx2=bx2[j],jy2=by2[j];
                float jar=(jx2-jx1+1.f)*(jy2-jy1+1.f);
                short jlb=slb[j];
                unsigned mm = cm;
                bool dead = false;
                while (mm) {
                    int b2 = __ffs(mm) - 1; mm &= mm - 1;
                    int i = cb + b2;
                    if (slb[i] != jlb) continue;
                    float ix1=bx1[i],iy1=by1[i],ix2=bx2[i],iy2=by2[i];
                    float iw=fmaxf(fminf(jx2,ix2)-fmaxf(jx1,ix1)+1.f,0.f);
                    float ih=fmaxf(fminf(jy2,iy2)-fmaxf(jy1,iy1)+1.f,0.f);
                    float inter=iw*ih;
                    float iar=(ix2-ix1+1.f)*(iy2-iy1+1.f);
                    if (inter/(jar+iar-inter+1e-9f) > 0.5f) { dead = true; break; }
                }
                if (dead) keep[j] = 0;
            }
        }
        __syncthreads();
    }

    if (tid < 32) {
        int lane = tid, cnt = 0;
        for (int pass = 0; pass < 2; pass++) {
            for (int b2 = 0; b2 < NCAND && cnt < 100; b2 += 32) {
                int i = b2 + lane;
                bool pr = (i < NCAND) && ((pass == 0) ? (keep[i] != 0) : (keep[i] == 0));
                unsigned w = __ballot_sync(~0u, pr);
                int pre = __popc(w & ((1u << lane) - 1u));
                if (pr && cnt + pre < 100) s_ti[cnt + pre] = i;
                cnt += __popc(w);
            }
            if (cnt > 100) cnt = 100;
        }
    }
    __syncthreads();

    if (tid < 100) {
        int p = s_ti[tid];
        unsigned ord = (unsigned)(skey[p] >> 32);
        float s = (ord & 0x80000000u) ? __uint_as_float(ord ^ 0x80000000u)
                                      : __uint_as_float(~ord);
        float tv = keep[p] ? s : -1.f;
        out[n*400 + tid*4 + 0] = bx1[p];
        out[n*400 + tid*4 + 1] = by1[p];
        out[n*400 + tid*4 + 2] = bx2[p];
        out[n*400 + tid*4 + 3] = by2[p];
        out[1600 + n*100 + tid] = tv;
        out[2000 + n*100 + tid] = (float)slb[p];
        out[2400 + n*100 + tid] = (tv > 0.f) ? 1.f : 0.f;
    }
}

extern "C" void kernel_launch(void* const* d_in, const int* in_sizes, int n_in,
                              void* d_out, int out_size) {
    const float *cls[3], *gau[3];
    if (in_sizes[0] == in_sizes[1]) {          // interleaved
        cls[0]=(const float*)d_in[0]; gau[0]=(const float*)d_in[1];
        cls[1]=(const float*)d_in[2]; gau[1]=(const float*)d_in[3];
        cls[2]=(const float*)d_in[4]; gau[2]=(const float*)d_in[5];
    } else {                                   // grouped
        cls[0]=(const float*)d_in[0]; cls[1]=(const float*)d_in[1]; cls[2]=(const float*)d_in[2];
        gau[0]=(const float*)d_in[3]; gau[1]=(const float*)d_in[4]; gau[2]=(const float*)d_in[5];
    }
    float* out = (float*)d_out;

    k_zero<<<2048, 256>>>();

    const int Hs[3]={160,80,40}, Ws[3]={256,128,64};
    const int caps[3] = {CAP0, CAP1, CAP2};
    const int loffs[3] = {0, CAP0, CAP0 + CAP1};
    for (int l = 0; l < 3; l++) {
        int tot = NIMG * CCH * Hs[l] * Ws[l];
        k_score<<<(tot + 255) / 256, 256>>>(cls[l], gau[l], Hs[l], Ws[l], l, caps[l], loffs[l]);
    }
    k_select<<<NIMG * 3, 1024>>>();
    k_solve<<<(NIMG * NCAND + 255) / 256, 256>>>(gau[0], gau[1], gau[2]);
    k_nms<<<NIMG, 1024>>>(out);
}

// round 6
// speedup vs baseline: 1.7583x; 1.4744x over previous
#include <cuda_runtime.h>
#include <cstdint>

#define NIMG  4
#define CCH   80
#define TOPN  500
#define NCAND 1500
#define NBINS (1<<18)
#define CAP0 524288
#define CAP1 131072
#define CAP2 65536
#define CAPI (CAP0+CAP1+CAP2)
#define BOX_LOGIT_THRESH (-2.9444389791664403f)

__device__ unsigned long long g_cand[NIMG * CAPI];
__device__ unsigned int       g_hist[NIMG * 3 * NBINS];
__device__ unsigned int       g_cnt[NIMG * 3];
__device__ unsigned long long g_top[NIMG * NCAND];
__device__ float g_x1[NIMG*NCAND], g_y1[NIMG*NCAND], g_x2[NIMG*NCAND], g_y2[NIMG*NCAND];
__device__ int   g_lb[NIMG*NCAND];
__device__ unsigned char g_vd[NIMG*NCAND];

__constant__ int c_cap[3]  = {CAP0, CAP1, CAP2};
__constant__ int c_loff[3] = {0, CAP0, CAP0 + CAP1};

__device__ __forceinline__ float sigm(float x) {
    if (x >= 0.f) return 1.f / (1.f + expf(-x));
    float e = expf(x); return e / (1.f + e);
}

__device__ void bitonic_desc(unsigned long long* a, int sz) {
    for (int k = 2; k <= sz; k <<= 1)
        for (int j = k >> 1; j > 0; j >>= 1) {
            for (int t = threadIdx.x; t < sz; t += blockDim.x) {
                int ixj = t ^ j;
                if (ixj > t) {
                    unsigned long long u = a[t], v = a[ixj];
                    bool sw = ((t & k) == 0) ? (u < v) : (u > v);
                    if (sw) { a[t] = v; a[ixj] = u; }
                }
            }
            __syncthreads();
        }
}

__global__ void k_zero() {
    int tid = blockIdx.x * blockDim.x + threadIdx.x;
    int st = gridDim.x * blockDim.x;
    uint4* h4 = (uint4*)g_hist;
    for (int i = tid; i < (NIMG * 3 * NBINS) / 4; i += st)
        h4[i] = make_uint4(0u, 0u, 0u, 0u);
    if (tid < NIMG * 3) g_cnt[tid] = 0;
}

// one thread per 4 consecutive pixels; all index math constant-folded
template<int H, int W, int LVL, int CAPL, int LOFF>
__global__ void __launch_bounds__(256) k_score4(const float* __restrict__ cls,
                                                const float* __restrict__ gau) {
    constexpr int hw  = H * W;
    constexpr int CHW = CCH * hw;
    constexpr int QPI = CHW / 4;
    int q   = blockIdx.x * 256 + threadIdx.x;
    int n   = q / QPI;
    int pix = q * 4;
    int r   = pix - n * CHW;          // pixel index within image
    int pp  = r % hw;                 // hw is NOT a power of two — must use %
    int y   = pp / W;
    int x0  = pp & (W - 1);           // W IS a power of two

    float4 cl4 = *(const float4*)(cls + (size_t)pix);
    bool iy = (y > 0) & (y < H - 1);
    bool t0 = iy && (x0 > 0)     && (cl4.x > BOX_LOGIT_THRESH);
    bool t1 = iy &&                 (cl4.y > BOX_LOGIT_THRESH);
    bool t2 = iy &&                 (cl4.z > BOX_LOGIT_THRESH);
    bool t3 = iy && (x0 < W - 4) && (cl4.w > BOX_LOGIT_THRESH);

    unsigned sbv[4]; int rrv[4]; int cnt = 0;

    if (t0 | t1 | t2 | t3) {
        const float* G = gau + (size_t)(pix - pp);    // (n,c,0,0)
        bool hasL = x0 > 0, hasR = x0 < W - 4;
        const float4* Gm = (const float4*)(G + pp - W);
        const float4* Gc = (const float4*)(G + pp);
        const float4* Gp = (const float4*)(G + pp + W);
        float4 z = make_float4(0.f, 0.f, 0.f, 0.f);
        float4 u0 = hasL ? Gm[-1] : z, u1 = Gm[0], u2 = hasR ? Gm[1] : z;
        float4 c0 = hasL ? Gc[-1] : z, c1 = Gc[0], c2 = hasR ? Gc[1] : z;
        float4 d0 = hasL ? Gp[-1] : z, d1 = Gp[0], d2 = hasR ? Gp[1] : z;

        if (t0) {
            float gc = c1.x;
            float m = fmaxf(fmaxf(u0.w, u1.x), u1.y);
            m = fmaxf(m, fmaxf(c0.w, c1.y));
            m = fmaxf(m, fmaxf(fmaxf(d0.w, d1.x), d1.y));
            if (gc >= m) {
                float sc = sqrtf(sigm(cl4.x) * sigm(gc));
                sbv[cnt] = __float_as_uint(sc); rrv[cnt] = r + 0; cnt++;
            }
        }
        if (t1) {
            float gc = c1.y;
            float m = fmaxf(fmaxf(u1.x, u1.y), u1.z);
            m = fmaxf(m, fmaxf(c1.x, c1.z));
            m = fmaxf(m, fmaxf(fmaxf(d1.x, d1.y), d1.z));
            if (gc >= m) {
                float sc = sqrtf(sigm(cl4.y) * sigm(gc));
                sbv[cnt] = __float_as_uint(sc); rrv[cnt] = r + 1; cnt++;
            }
        }
        if (t2) {
            float gc = c1.z;
            float m = fmaxf(fmaxf(u1.y, u1.z), u1.w);
            m = fmaxf(m, fmaxf(c1.y, c1.w));
            m = fmaxf(m, fmaxf(fmaxf(d1.y, d1.z), d1.w));
            if (gc >= m) {
                float sc = sqrtf(sigm(cl4.z) * sigm(gc));
                sbv[cnt] = __float_as_uint(sc); rrv[cnt] = r + 2; cnt++;
            }
        }
        if (t3) {
            float gc = c1.w;
            float m = fmaxf(fmaxf(u1.z, u1.w), u2.x);
            m = fmaxf(m, fmaxf(c1.z, c2.x));
            m = fmaxf(m, fmaxf(fmaxf(d1.z, d1.w), d2.x));
            if (gc >= m) {
                float sc = sqrtf(sigm(cl4.w) * sigm(gc));
                sbv[cnt] = __float_as_uint(sc); rrv[cnt] = r + 3; cnt++;
            }
        }
    }

    // warp scan for slot allocation (n, hence b, is warp-uniform: QPI % 32 == 0)
    int lane = threadIdx.x & 31;
    unsigned cinc = (unsigned)cnt;
    #pragma unroll
    for (int off = 1; off < 32; off <<= 1) {
        unsigned t = __shfl_up_sync(0xFFFFFFFFu, cinc, off);
        if (lane >= off) cinc += t;
    }
    unsigned total = __shfl_sync(0xFFFFFFFFu, cinc, 31);
    if (total == 0u) return;
    int b = n * 3 + LVL;
    unsigned base = 0;
    if (lane == 0) base = atomicAdd(&g_cnt[b], total);
    base = __shfl_sync(0xFFFFFFFFu, base, 0);
    unsigned pre = cinc - (unsigned)cnt;
    for (int k = 0; k < cnt; k++) {
        atomicAdd(&g_hist[(size_t)b * NBINS + (sbv[k] >> 12)], 1u);
        unsigned slot = base + pre + (unsigned)k;
        if (slot < (unsigned)CAPL)
            g_cand[(size_t)n * CAPI + LOFF + slot] =
                ((unsigned long long)sbv[k] << 32) | (unsigned)(~rrv[k]);
    }
}

// top-500 select per (image, level), with box solve fused at the end
__global__ void __launch_bounds__(1024) k_select(const float* __restrict__ g0,
                                                 const float* __restrict__ g1,
                                                 const float* __restrict__ g2) {
    int b = blockIdx.x;
    int n = b / 3, lvl = b % 3;
    const unsigned int* hist = &g_hist[(size_t)b * NBINS];
    __shared__ unsigned int cs[1024];
    __shared__ unsigned int fine[256];
    __shared__ unsigned long long sel[4096];
    __shared__ unsigned int sT, sM;
    __shared__ int s_tc;
    int tid = threadIdx.x;

    const uint4* h4 = (const uint4*)hist;
    unsigned s = 0;
    int b4 = tid * 64;
    #pragma unroll 16
    for (int i = 0; i < 64; i++) {
        uint4 v = h4[b4 + i];
        s += v.x + v.y + v.z + v.w;
    }
    cs[tid] = s;
    if (tid == 0) sM = 0;
    __syncthreads();

    if (tid == 0) {
        unsigned acc = 0; int tc = -1;
        for (int t = 1023; t >= 0; --t) { acc += cs[t]; if (acc >= TOPN) { tc = t; break; } }
        s_tc = tc;
        cs[1023] = (tc >= 0) ? (acc - cs[tc]) : 0;
    }
    __syncthreads();
    int tc = s_tc;
    if (tc >= 0 && tid < 256) fine[tid] = hist[tc * 256 + tid];
    __syncthreads();
    if (tid == 0) {
        unsigned T = 0;
        if (tc >= 0) {
            unsigned acc2 = cs[1023];
            for (int bb = 255; bb >= 0; --bb) {
                acc2 += fine[bb];
                if (acc2 >= TOPN) { T = (unsigned)(tc * 256 + bb); break; }
            }
        }
        sT = T;
    }
    __syncthreads();
    unsigned T = sT;

    unsigned cnt = min(g_cnt[b], (unsigned)c_cap[lvl]);
    const unsigned long long* cand = &g_cand[(size_t)n * CAPI + c_loff[lvl]];
    for (unsigned i = tid; i < cnt; i += blockDim.x) {
        unsigned long long k = cand[i];
        if ((unsigned)(k >> 44) >= T) {
            unsigned p = atomicAdd(&sM, 1u);
            if (p < 4096) sel[p] = k;
        }
    }
    __syncthreads();
    unsigned mM = min(sM, 4096u);
    for (int i = tid; i < 4096; i += blockDim.x)
        if ((unsigned)i >= mM) sel[i] = 0ull;
    __syncthreads();
    bitonic_desc(sel, 4096);

    // write top-500 + fused box solve
    if (tid < TOPN) {
        int t = n * NCAND + lvl * TOPN + tid;
        unsigned long long key = sel[tid];
        g_top[t] = key;

        int H, W, step; const float* G;
        if (lvl == 0)      { H = 160; W = 256; step = 8;  G = g0; }
        else if (lvl == 1) { H = 80;  W = 128; step = 16; G = g1; }
        else               { H = 40;  W = 64;  step = 32; G = g2; }
        float sc = __uint_as_float((unsigned)(key >> 32));
        unsigned flat = ~(unsigned)key;
        int hw = H * W;
        if (!(sc > 0.f) || flat >= (unsigned)(CCH * hw)) {
            g_x1[t]=0.f; g_y1[t]=0.f; g_x2[t]=0.f; g_y2[t]=0.f; g_lb[t]=1; g_vd[t]=0;
        } else {
            int c = (int)(flat / hw);
            int rem = (int)(flat - (unsigned)c * hw);
            int y = rem / W, x = rem - y * W;
            const float* B = G + ((size_t)(n * CCH + c)) * hw;
            auto LV = [&](int yy, int xx) -> float {
                yy = min(max(yy, 0), H - 1);
                xx = min(max(xx, 0), W - 1);
                return log1pf(expf(-B[yy * W + xx])) * 0.125f;
            };
            float l0 = LV(y, x);
            float lxp = LV(y, x+1), lxm = LV(y, x-1);
            float lyp = LV(y+1, x), lym = LV(y-1, x);
            float Ax = (lxp + lxm - 2.f * l0) * 0.5f;
            float Ay = (lyp + lym - 2.f * l0) * 0.5f;
            bool px = Ax > 1e-8f, py = Ay > 1e-8f;
            float Axs = px ? Ax : 1.f, Ays = py ? Ay : 1.f;
            float mux = (float)x - (lxp - lxm) / (4.f * Axs);
            float muy = (float)y - (lyp - lym) / (4.f * Ays);
            float wb = (px ? rsqrtf(2.f * Axs) : 0.f) * (float)step;
            float hb = (py ? rsqrtf(2.f * Ays) : 0.f) * (float)step;
            float x1 = mux * (float)step - 0.5f * wb + (float)(step - 1) * 0.5f;
            float y1 = muy * (float)step - 0.5f * hb + (float)(step - 1) * 0.5f;
            bool vd = (wb > 0.f) && (hb > 0.f);
            float x2 = x1 + wb - 1.f, y2 = y1 + hb - 1.f;
            g_x1[t] = fminf(fmaxf(x1, 0.f), 2047.f);
            g_x2[t] = fminf(fmaxf(x2, 0.f), 2047.f);
            g_y1[t] = fminf(fmaxf(y1, 0.f), 1279.f);
            g_y2[t] = fminf(fmaxf(y2, 0.f), 1279.f);
            g_lb[t] = c + 1; g_vd[t] = vd ? 1 : 0;
        }
    }
}

__global__ void __launch_bounds__(1024) k_nms(float* __restrict__ out) {
    __shared__ unsigned long long skey[2048];
    __shared__ float bx1[NCAND], by1[NCAND], bx2[NCAND], by2[NCAND];
    __shared__ short slb[NCAND];
    __shared__ unsigned char keep[NCAND];
    __shared__ int s_ti[100];
    __shared__ unsigned int s_cm;
    int n = blockIdx.x, tid = threadIdx.x;

    for (int p = tid; p < 2048; p += 1024) {
        unsigned long long kk = 0ull;
        if (p < NCAND) {
            int gi = n * NCAND + p;
            float sc = __uint_as_float((unsigned)(g_top[gi] >> 32));
            float sv = g_vd[gi] ? sc : -1.f;
            unsigned bits = __float_as_uint(sv);
            unsigned ord = (bits & 0x80000000u) ? ~bits : (bits | 0x80000000u);
            kk = ((unsigned long long)ord << 32) | (0xFFFFFFFFu - (unsigned)p);
        }
        skey[p] = kk;
    }
    __syncthreads();
    bitonic_desc(skey, 2048);

    for (int p = tid; p < NCAND; p += 1024) {
        int pos = (int)(0xFFFFFFFFu - (unsigned)skey[p]);
        int gi = n * NCAND + pos;
        bx1[p]=g_x1[gi]; by1[p]=g_y1[gi]; bx2[p]=g_x2[gi]; by2[p]=g_y2[gi];
        slb[p]=(short)g_lb[gi]; keep[p]=g_vd[gi];
    }
    __syncthreads();

    for (int cb = 0; cb < NCAND; cb += 32) {
        if (tid < 32) {
            int l = tid, i = cb + l;
            bool in = i < NCAND;
            bool alive = false;
            unsigned sup = 0;
            if (in) {
                float ax1=bx1[i], ay1=by1[i], ax2=bx2[i], ay2=by2[i];
                float aar=(ax2-ax1+1.f)*(ay2-ay1+1.f);
                short alab=slb[i];
                alive = keep[i]!=0;
                for (int m = 0; m < l; m++) {
                    int im = cb + m;
                    if (slb[im] != alab) continue;
                    float ix1=bx1[im], iy1=by1[im], ix2=bx2[im], iy2=by2[im];
                    float iw=fmaxf(fminf(ax2,ix2)-fmaxf(ax1,ix1)+1.f,0.f);
                    float ih=fmaxf(fminf(ay2,iy2)-fmaxf(ay1,iy1)+1.f,0.f);
                    float inter=iw*ih;
                    float iar=(ix2-ix1+1.f)*(iy2-iy1+1.f);
                    if (inter/(aar+iar-inter+1e-9f) > 0.5f) sup |= (1u << m);
                }
            }
            #pragma unroll 1
            for (int m = 0; m < 31; m++) {
                unsigned bal = __ballot_sync(0xFFFFFFFFu, alive);
                if (l > m && ((bal >> m) & 1u) && ((sup >> m) & 1u)) alive = false;
            }
            if (in) keep[i] = alive ? 1 : 0;
            unsigned cm = __ballot_sync(0xFFFFFFFFu, alive && in);
            if (l == 0) s_cm = cm;
        }
        __syncthreads();
        unsigned cm = s_cm;
        if (cm) {
            for (int j = cb + 32 + tid; j < NCAND; j += 1024) {
                if (!keep[j]) continue;
                float jx1=bx1[j],jy1=by1[j],jx2=bx2[j],jy2=by2[j];
                float jar=(jx2-jx1+1.f)*(jy2-jy1+1.f);
                short jlb=slb[j];
                unsigned mm = cm;
                bool dead = false;
                while (mm) {
                    int b2 = __ffs(mm) - 1; mm &= mm - 1;
                    int i = cb + b2;
                    if (slb[i] != jlb) continue;
                    float ix1=bx1[i],iy1=by1[i],ix2=bx2[i],iy2=by2[i];
                    float iw=fmaxf(fminf(jx2,ix2)-fmaxf(jx1,ix1)+1.f,0.f);
                    float ih=fmaxf(fminf(jy2,iy2)-fmaxf(jy1,iy1)+1.f,0.f);
                    float inter=iw*ih;
                    float iar=(ix2-ix1+1.f)*(iy2-iy1+1.f);
                    if (inter/(jar+iar-inter+1e-9f) > 0.5f) { dead = true; break; }
                }
                if (dead) keep[j] = 0;
            }
        }
        __syncthreads();
    }

    if (tid < 32) {
        int lane = tid, cnt = 0;
        for (int pass = 0; pass < 2; pass++) {
            for (int b2 = 0; b2 < NCAND && cnt < 100; b2 += 32) {
                int i = b2 + lane;
                bool pr = (i < NCAND) && ((pass == 0) ? (keep[i] != 0) : (keep[i] == 0));
                unsigned w = __ballot_sync(~0u, pr);
                int pre = __popc(w & ((1u << lane) - 1u));
                if (pr && cnt + pre < 100) s_ti[cnt + pre] = i;
                cnt += __popc(w);
            }
            if (cnt > 100) cnt = 100;
        }
    }
    __syncthreads();

    if (tid < 100) {
        int p = s_ti[tid];
        unsigned ord = (unsigned)(skey[p] >> 32);
        float s = (ord & 0x80000000u) ? __uint_as_float(ord ^ 0x80000000u)
                                      : __uint_as_float(~ord);
        float tv = keep[p] ? s : -1.f;
        out[n*400 + tid*4 + 0] = bx1[p];
        out[n*400 + tid*4 + 1] = by1[p];
        out[n*400 + tid*4 + 2] = bx2[p];
        out[n*400 + tid*4 + 3] = by2[p];
        out[1600 + n*100 + tid] = tv;
        out[2000 + n*100 + tid] = (float)slb[p];
        out[2400 + n*100 + tid] = (tv > 0.f) ? 1.f : 0.f;
    }
}

extern "C" void kernel_launch(void* const* d_in, const int* in_sizes, int n_in,
                              void* d_out, int out_size) {
    const float *cls[3], *gau[3];
    if (in_sizes[0] == in_sizes[1]) {          // interleaved
        cls[0]=(const float*)d_in[0]; gau[0]=(const float*)d_in[1];
        cls[1]=(const float*)d_in[2]; gau[1]=(const float*)d_in[3];
        cls[2]=(const float*)d_in[4]; gau[2]=(const float*)d_in[5];
    } else {                                   // grouped
        cls[0]=(const float*)d_in[0]; cls[1]=(const float*)d_in[1]; cls[2]=(const float*)d_in[2];
        gau[0]=(const float*)d_in[3]; gau[1]=(const float*)d_in[4]; gau[2]=(const float*)d_in[5];
    }
    float* out = (float*)d_out;

    k_zero<<<2048, 256>>>();

    k_score4<160,256,0,CAP0,0>        <<<12800, 256>>>(cls[0], gau[0]);
    k_score4<80, 128,1,CAP1,CAP0>     <<<3200,  256>>>(cls[1], gau[1]);
    k_score4<40, 64, 2,CAP2,CAP0+CAP1><<<800,   256>>>(cls[2], gau[2]);

    k_select<<<NIMG * 3, 1024>>>(gau[0], gau[1], gau[2]);
    k_nms<<<NIMG, 1024>>>(out);
}

// round 7
// speedup vs baseline: 1.9518x; 1.1101x over previous
#include <cuda_runtime.h>
#include <cstdint>

#define NIMG  4
#define CCH   80
#define TOPN  500
#define NCAND 1500
#define CAP0 524288
#define CAP1 131072
#define CAP2 65536
#define CAPI (CAP0+CAP1+CAP2)
#define BOX_LOGIT_THRESH (-2.9444389791664403f)

__device__ unsigned long long g_cand[NIMG * CAPI];
__device__ unsigned int       g_cnt[NIMG * 3];
__device__ unsigned long long g_top[NIMG * NCAND];
__device__ float g_x1[NIMG*NCAND], g_y1[NIMG*NCAND], g_x2[NIMG*NCAND], g_y2[NIMG*NCAND];
__device__ int   g_lb[NIMG*NCAND];
__device__ unsigned char g_vd[NIMG*NCAND];

__constant__ int c_cap[3]  = {CAP0, CAP1, CAP2};
__constant__ int c_loff[3] = {0, CAP0, CAP0 + CAP1};

__device__ __forceinline__ float sigm(float x) {
    if (x >= 0.f) return 1.f / (1.f + expf(-x));
    float e = expf(x); return e / (1.f + e);
}

__device__ void bitonic_desc(unsigned long long* a, int sz) {
    for (int k = 2; k <= sz; k <<= 1)
        for (int j = k >> 1; j > 0; j >>= 1) {
            for (int t = threadIdx.x; t < sz; t += blockDim.x) {
                int ixj = t ^ j;
                if (ixj > t) {
                    unsigned long long u = a[t], v = a[ixj];
                    bool sw = ((t & k) == 0) ? (u < v) : (u > v);
                    if (sw) { a[t] = v; a[ixj] = u; }
                }
            }
            __syncthreads();
        }
}

__global__ void k_zcnt() {
    if (threadIdx.x < NIMG * 3) g_cnt[threadIdx.x] = 0;
}

// one thread per 4 consecutive pixels; all index math constant-folded
template<int H, int W, int LVL, int CAPL, int LOFF>
__device__ __forceinline__ void score_body(const float* __restrict__ cls,
                                           const float* __restrict__ gau, int bid) {
    constexpr int hw  = H * W;
    constexpr int CHW = CCH * hw;
    constexpr int QPI = CHW / 4;
    int q   = bid * 256 + threadIdx.x;
    int n   = q / QPI;
    int pix = q * 4;
    int r   = pix - n * CHW;
    int pp  = r % hw;                 // hw is NOT a power of two
    int y   = pp / W;
    int x0  = pp & (W - 1);           // W IS a power of two

    float4 cl4 = *(const float4*)(cls + (size_t)pix);
    bool iy = (y > 0) & (y < H - 1);
    bool t0 = iy && (x0 > 0)     && (cl4.x > BOX_LOGIT_THRESH);
    bool t1 = iy &&                 (cl4.y > BOX_LOGIT_THRESH);
    bool t2 = iy &&                 (cl4.z > BOX_LOGIT_THRESH);
    bool t3 = iy && (x0 < W - 4) && (cl4.w > BOX_LOGIT_THRESH);

    unsigned sbv[4]; int rrv[4]; int cnt = 0;

    if (t0 | t1 | t2 | t3) {
        const float* G = gau + (size_t)(pix - pp);
        bool hasL = x0 > 0, hasR = x0 < W - 4;
        const float4* Gm = (const float4*)(G + pp - W);
        const float4* Gc = (const float4*)(G + pp);
        const float4* Gp = (const float4*)(G + pp + W);
        float4 z = make_float4(0.f, 0.f, 0.f, 0.f);
        float4 u0 = hasL ? Gm[-1] : z, u1 = Gm[0], u2 = hasR ? Gm[1] : z;
        float4 c0 = hasL ? Gc[-1] : z, c1 = Gc[0], c2 = hasR ? Gc[1] : z;
        float4 d0 = hasL ? Gp[-1] : z, d1 = Gp[0], d2 = hasR ? Gp[1] : z;

        if (t0) {
            float gc = c1.x;
            float m = fmaxf(fmaxf(u0.w, u1.x), u1.y);
            m = fmaxf(m, fmaxf(c0.w, c1.y));
            m = fmaxf(m, fmaxf(fmaxf(d0.w, d1.x), d1.y));
            if (gc >= m) {
                float sc = sqrtf(sigm(cl4.x) * sigm(gc));
                sbv[cnt] = __float_as_uint(sc); rrv[cnt] = r + 0; cnt++;
            }
        }
        if (t1) {
            float gc = c1.y;
            float m = fmaxf(fmaxf(u1.x, u1.y), u1.z);
            m = fmaxf(m, fmaxf(c1.x, c1.z));
            m = fmaxf(m, fmaxf(fmaxf(d1.x, d1.y), d1.z));
            if (gc >= m) {
                float sc = sqrtf(sigm(cl4.y) * sigm(gc));
                sbv[cnt] = __float_as_uint(sc); rrv[cnt] = r + 1; cnt++;
            }
        }
        if (t2) {
            float gc = c1.z;
            float m = fmaxf(fmaxf(u1.y, u1.z), u1.w);
            m = fmaxf(m, fmaxf(c1.y, c1.w));
            m = fmaxf(m, fmaxf(fmaxf(d1.y, d1.z), d1.w));
            if (gc >= m) {
                float sc = sqrtf(sigm(cl4.z) * sigm(gc));
                sbv[cnt] = __float_as_uint(sc); rrv[cnt] = r + 2; cnt++;
            }
        }
        if (t3) {
            float gc = c1.w;
            float m = fmaxf(fmaxf(u1.z, u1.w), u2.x);
            m = fmaxf(m, fmaxf(c1.z, c2.x));
            m = fmaxf(m, fmaxf(fmaxf(d1.z, d1.w), d2.x));
            if (gc >= m) {
                float sc = sqrtf(sigm(cl4.w) * sigm(gc));
                sbv[cnt] = __float_as_uint(sc); rrv[cnt] = r + 3; cnt++;
            }
        }
    }

    // warp scan for slot allocation (n warp-uniform: QPI % 32 == 0)
    int lane = threadIdx.x & 31;
    unsigned cinc = (unsigned)cnt;
    #pragma unroll
    for (int off = 1; off < 32; off <<= 1) {
        unsigned t = __shfl_up_sync(0xFFFFFFFFu, cinc, off);
        if (lane >= off) cinc += t;
    }
    unsigned total = __shfl_sync(0xFFFFFFFFu, cinc, 31);
    if (total == 0u) return;
    int b = n * 3 + LVL;
    unsigned base = 0;
    if (lane == 0) base = atomicAdd(&g_cnt[b], total);
    base = __shfl_sync(0xFFFFFFFFu, base, 0);
    unsigned pre = cinc - (unsigned)cnt;
    #pragma unroll
    for (int k = 0; k < cnt; k++) {
        unsigned slot = base + pre + (unsigned)k;
        if (slot < (unsigned)CAPL)
            g_cand[(size_t)n * CAPI + LOFF + slot] =
                ((unsigned long long)sbv[k] << 32) | (unsigned)(~rrv[k]);
    }
}

__global__ void __launch_bounds__(256) k_score_all(
    const float* __restrict__ c0, const float* __restrict__ g0,
    const float* __restrict__ c1, const float* __restrict__ g1,
    const float* __restrict__ c2, const float* __restrict__ g2) {
    int bid = blockIdx.x;
    if (bid < 12800)       score_body<160,256,0,CAP0,0>        (c0, g0, bid);
    else if (bid < 16000)  score_body<80, 128,1,CAP1,CAP0>     (c1, g1, bid - 12800);
    else                   score_body<40, 64, 2,CAP2,CAP0+CAP1>(c2, g2, bid - 16000);
}

// top-500 select per (image, level): shared-mem 2-pass histogram over the
// candidate list (threshold granularity sb>>12, identical to the old global hist)
__global__ void __launch_bounds__(1024) k_select(const float* __restrict__ g0,
                                                 const float* __restrict__ g1,
                                                 const float* __restrict__ g2) {
    int b = blockIdx.x;
    int n = b / 3, lvl = b % 3;
    __shared__ unsigned int sh_c[1024];
    __shared__ unsigned int sh_f[256];
    __shared__ unsigned long long sel[4096];
    __shared__ unsigned int sT, sM, sAbove;
    __shared__ int sB;
    int tid = threadIdx.x;

    unsigned cnt = min(g_cnt[b], (unsigned)c_cap[lvl]);
    const unsigned long long* cand = &g_cand[(size_t)n * CAPI + c_loff[lvl]];

    sh_c[tid] = 0;
    if (tid == 0) { sM = 0; sB = -1; sAbove = 0; sT = 0; }
    __syncthreads();

    // pass 1: coarse histogram on sb>>20 (all candidate scores < 1.0 -> bin < 1016)
    for (unsigned i = tid; i < cnt; i += 1024) {
        unsigned hi = (unsigned)(cand[i] >> 32);
        atomicAdd(&sh_c[hi >> 20], 1u);
    }
    __syncthreads();

    // suffix sum over 1024 coarse bins (Hillis-Steele)
    for (int off = 1; off < 1024; off <<= 1) {
        unsigned v = sh_c[tid];
        if (tid + off < 1024) v += sh_c[tid + off];
        __syncthreads();
        sh_c[tid] = v;
        __syncthreads();
    }
    // crossing bin B: suffix[B] >= TOPN, suffix[B+1] < TOPN
    if (sh_c[tid] >= TOPN && (tid == 1023 || sh_c[tid + 1] < TOPN)) {
        sB = tid;
        sAbove = (tid == 1023) ? 0u : sh_c[tid + 1];
    }
    if (tid < 256) sh_f[tid] = 0;
    __syncthreads();
    int B = sB;
    unsigned above = sAbove;

    // pass 2: fine histogram within coarse bin B on (sb>>12)&255
    if (B >= 0) {
        for (unsigned i = tid; i < cnt; i += 1024) {
            unsigned hi = (unsigned)(cand[i] >> 32);
            if ((int)(hi >> 20) == B) atomicAdd(&sh_f[(hi >> 12) & 255], 1u);
        }
    }
    __syncthreads();
    for (int off = 1; off < 256; off <<= 1) {
        unsigned v = 0;
        if (tid < 256) { v = sh_f[tid]; if (tid + off < 256) v += sh_f[tid + off]; }
        __syncthreads();
        if (tid < 256) sh_f[tid] = v;
        __syncthreads();
    }
    if (B >= 0 && tid < 256) {
        unsigned cum = above + sh_f[tid];
        unsigned nxt = (tid == 255) ? above : above + sh_f[tid + 1];
        if (cum >= TOPN && nxt < TOPN) sT = ((unsigned)B << 8) | (unsigned)tid;
    }
    __syncthreads();
    unsigned T = sT;

    // pass 3: collect keys >= T, sort, emit top-500
    for (unsigned i = tid; i < cnt; i += 1024) {
        unsigned long long k = cand[i];
        if ((unsigned)(k >> 44) >= T) {
            unsigned p = atomicAdd(&sM, 1u);
            if (p < 4096) sel[p] = k;
        }
    }
    __syncthreads();
    unsigned mM = min(sM, 4096u);
    for (int i = tid; i < 4096; i += 1024)
        if ((unsigned)i >= mM) sel[i] = 0ull;
    __syncthreads();
    bitonic_desc(sel, 4096);

    // write top-500 + fused box solve
    if (tid < TOPN) {
        int t = n * NCAND + lvl * TOPN + tid;
        unsigned long long key = sel[tid];
        g_top[t] = key;

        int H, W, step; const float* G;
        if (lvl == 0)      { H = 160; W = 256; step = 8;  G = g0; }
        else if (lvl == 1) { H = 80;  W = 128; step = 16; G = g1; }
        else               { H = 40;  W = 64;  step = 32; G = g2; }
        float sc = __uint_as_float((unsigned)(key >> 32));
        unsigned flat = ~(unsigned)key;
        int hw = H * W;
        if (!(sc > 0.f) || flat >= (unsigned)(CCH * hw)) {
            g_x1[t]=0.f; g_y1[t]=0.f; g_x2[t]=0.f; g_y2[t]=0.f; g_lb[t]=1; g_vd[t]=0;
        } else {
            int c = (int)(flat / hw);
            int rem = (int)(flat - (unsigned)c * hw);
            int y = rem / W, x = rem - y * W;
            const float* Bp = G + ((size_t)(n * CCH + c)) * hw;
            auto LV = [&](int yy, int xx) -> float {
                yy = min(max(yy, 0), H - 1);
                xx = min(max(xx, 0), W - 1);
                return log1pf(expf(-Bp[yy * W + xx])) * 0.125f;
            };
            float l0 = LV(y, x);
            float lxp = LV(y, x+1), lxm = LV(y, x-1);
            float lyp = LV(y+1, x), lym = LV(y-1, x);
            float Ax = (lxp + lxm - 2.f * l0) * 0.5f;
            float Ay = (lyp + lym - 2.f * l0) * 0.5f;
            bool px = Ax > 1e-8f, py = Ay > 1e-8f;
            float Axs = px ? Ax : 1.f, Ays = py ? Ay : 1.f;
            float mux = (float)x - (lxp - lxm) / (4.f * Axs);
            float muy = (float)y - (lyp - lym) / (4.f * Ays);
            float wb = (px ? rsqrtf(2.f * Axs) : 0.f) * (float)step;
            float hb = (py ? rsqrtf(2.f * Ays) : 0.f) * (float)step;
            float x1 = mux * (float)step - 0.5f * wb + (float)(step - 1) * 0.5f;
            float y1 = muy * (float)step - 0.5f * hb + (float)(step - 1) * 0.5f;
            bool vd = (wb > 0.f) && (hb > 0.f);
            float x2 = x1 + wb - 1.f, y2 = y1 + hb - 1.f;
            g_x1[t] = fminf(fmaxf(x1, 0.f), 2047.f);
            g_x2[t] = fminf(fmaxf(x2, 0.f), 2047.f);
            g_y1[t] = fminf(fmaxf(y1, 0.f), 1279.f);
            g_y2[t] = fminf(fmaxf(y2, 0.f), 1279.f);
            g_lb[t] = c + 1; g_vd[t] = vd ? 1 : 0;
        }
    }
}

__global__ void __launch_bounds__(1024) k_nms(float* __restrict__ out) {
    __shared__ unsigned long long skey[2048];
    __shared__ float bx1[NCAND], by1[NCAND], bx2[NCAND], by2[NCAND];
    __shared__ short slb[NCAND];
    __shared__ unsigned char keep[NCAND];
    __shared__ unsigned int sh_sup[32];
    __shared__ int s_ti[100];
    __shared__ unsigned int s_cm;
    int n = blockIdx.x, tid = threadIdx.x;

    for (int p = tid; p < 2048; p += 1024) {
        unsigned long long kk = 0ull;
        if (p < NCAND) {
            int gi = n * NCAND + p;
            float sc = __uint_as_float((unsigned)(g_top[gi] >> 32));
            float sv = g_vd[gi] ? sc : -1.f;
            unsigned bits = __float_as_uint(sv);
            unsigned ord = (bits & 0x80000000u) ? ~bits : (bits | 0x80000000u);
            kk = ((unsigned long long)ord << 32) | (0xFFFFFFFFu - (unsigned)p);
        }
        skey[p] = kk;
    }
    __syncthreads();
    bitonic_desc(skey, 2048);

    for (int p = tid; p < NCAND; p += 1024) {
        int pos = (int)(0xFFFFFFFFu - (unsigned)skey[p]);
        int gi = n * NCAND + pos;
        bx1[p]=g_x1[gi]; by1[p]=g_y1[gi]; bx2[p]=g_x2[gi]; by2[p]=g_y2[gi];
        slb[p]=(short)g_lb[gi]; keep[p]=g_vd[gi];
    }
    __syncthreads();

    int w = tid >> 5, l = tid & 31;
    for (int cb = 0; cb < NCAND; cb += 32) {
        // 32 warps: warp w computes suppression row for box i=cb+w vs j=cb+l (l<w)
        int i = cb + w, j = cb + l;
        bool sb_ = false;
        if (i < NCAND && l < w && slb[i] == slb[j]) {
            float ix1=bx1[i], iy1=by1[i], ix2=bx2[i], iy2=by2[i];
            float jx1=bx1[j], jy1=by1[j], jx2=bx2[j], jy2=by2[j];
            float iar=(ix2-ix1+1.f)*(iy2-iy1+1.f);
            float jar=(jx2-jx1+1.f)*(jy2-jy1+1.f);
            float iw=fmaxf(fminf(ix2,jx2)-fmaxf(ix1,jx1)+1.f,0.f);
            float ih=fmaxf(fminf(iy2,jy2)-fmaxf(iy1,jy1)+1.f,0.f);
            float inter=iw*ih;
            sb_ = inter/(iar+jar-inter+1e-9f) > 0.5f;
        }
        unsigned row = __ballot_sync(0xFFFFFFFFu, sb_);
        if (l == 0) sh_sup[w] = row;
        unsigned valid = 0;
        if (w == 0) {
            bool kv = (cb + l < NCAND) && keep[cb + l];
            valid = __ballot_sync(0xFFFFFFFFu, kv);
        }
        __syncthreads();
        if (tid == 0) {
            unsigned alive = valid;
            #pragma unroll 1
            for (int m = 1; m < 32; m++) {
                if ((alive >> m) & 1u) {
                    if (sh_sup[m] & alive & ((1u << m) - 1u)) alive &= ~(1u << m);
                }
            }
            s_cm = alive;
        }
        __syncthreads();
        unsigned cm = s_cm;
        if (tid < 32 && cb + tid < NCAND) keep[cb + tid] = (cm >> tid) & 1u;
        if (cm) {
            for (int jj = cb + 32 + tid; jj < NCAND; jj += 1024) {
                if (!keep[jj]) continue;
                float jx1=bx1[jj],jy1=by1[jj],jx2=bx2[jj],jy2=by2[jj];
                float jar=(jx2-jx1+1.f)*(jy2-jy1+1.f);
                short jlb=slb[jj];
                unsigned mm = cm;
                bool dead = false;
                while (mm) {
                    int b2 = __ffs(mm) - 1; mm &= mm - 1;
                    int ii = cb + b2;
                    if (slb[ii] != jlb) continue;
                    float ix1=bx1[ii],iy1=by1[ii],ix2=bx2[ii],iy2=by2[ii];
                    float iw=fmaxf(fminf(jx2,ix2)-fmaxf(jx1,ix1)+1.f,0.f);
                    float ih=fmaxf(fminf(jy2,iy2)-fmaxf(jy1,iy1)+1.f,0.f);
                    float inter=iw*ih;
                    float iar=(ix2-ix1+1.f)*(iy2-iy1+1.f);
                    if (inter/(jar+iar-inter+1e-9f) > 0.5f) { dead = true; break; }
                }
                if (dead) keep[jj] = 0;
            }
        }
        __syncthreads();
    }

    if (tid < 32) {
        int lane = tid, cnt = 0;
        for (int pass = 0; pass < 2; pass++) {
            for (int b2 = 0; b2 < NCAND && cnt < 100; b2 += 32) {
                int i2 = b2 + lane;
                bool pr = (i2 < NCAND) && ((pass == 0) ? (keep[i2] != 0) : (keep[i2] == 0));
                unsigned ww = __ballot_sync(~0u, pr);
                int pre = __popc(ww & ((1u << lane) - 1u));
                if (pr && cnt + pre < 100) s_ti[cnt + pre] = i2;
                cnt += __popc(ww);
            }
            if (cnt > 100) cnt = 100;
        }
    }
    __syncthreads();

    if (tid < 100) {
        int p = s_ti[tid];
        unsigned ord = (unsigned)(skey[p] >> 32);
        float s = (ord & 0x80000000u) ? __uint_as_float(ord ^ 0x80000000u)
                                      : __uint_as_float(~ord);
        float tv = keep[p] ? s : -1.f;
        out[n*400 + tid*4 + 0] = bx1[p];
        out[n*400 + tid*4 + 1] = by1[p];
        out[n*400 + tid*4 + 2] = bx2[p];
        out[n*400 + tid*4 + 3] = by2[p];
        out[1600 + n*100 + tid] = tv;
        out[2000 + n*100 + tid] = (float)slb[p];
        out[2400 + n*100 + tid] = (tv > 0.f) ? 1.f : 0.f;
    }
}

extern "C" void kernel_launch(void* const* d_in, const int* in_sizes, int n_in,
                              void* d_out, int out_size) {
    const float *cls[3], *gau[3];
    if (in_sizes[0] == in_sizes[1]) {          // interleaved
        cls[0]=(const float*)d_in[0]; gau[0]=(const float*)d_in[1];
        cls[1]=(const float*)d_in[2]; gau[1]=(const float*)d_in[3];
        cls[2]=(const float*)d_in[4]; gau[2]=(const float*)d_in[5];
    } else {                                   // grouped
        cls[0]=(const float*)d_in[0]; cls[1]=(const float*)d_in[1]; cls[2]=(const float*)d_in[2];
        gau[0]=(const float*)d_in[3]; gau[1]=(const float*)d_in[4]; gau[2]=(const float*)d_in[5];
    }
    float* out = (float*)d_out;

    k_zcnt<<<1, 32>>>();
    k_score_all<<<16800, 256>>>(cls[0], gau[0], cls[1], gau[1], cls[2], gau[2]);
    k_select<<<NIMG * 3, 1024>>>(gau[0], gau[1], gau[2]);
    k_nms<<<NIMG, 1024>>>(out);
}

// round 9
// speedup vs baseline: 5.8296x; 2.9867x over previous
#include <cuda_runtime.h>
#include <cstdint>

#define NIMG  4
#define CCH   80
#define TOPN  500
#define NCAND 1500
#define CAP0 524288
#define CAP1 131072
#define CAP2 65536
#define CAPI (CAP0+CAP1+CAP2)
#define BOX_LOGIT_THRESH (-2.9444389791664403f)

__device__ unsigned long long g_cand[NIMG * CAPI];
__device__ unsigned int       g_cnt[NIMG * 3];
__device__ unsigned long long g_top[NIMG * NCAND];
__device__ float g_x1[NIMG*NCAND], g_y1[NIMG*NCAND], g_x2[NIMG*NCAND], g_y2[NIMG*NCAND];
__device__ int   g_lb[NIMG*NCAND];
__device__ unsigned char g_vd[NIMG*NCAND];

__constant__ int c_cap[3]  = {CAP0, CAP1, CAP2};
__constant__ int c_loff[3] = {0, CAP0, CAP0 + CAP1};

__device__ __forceinline__ float sigm(float x) {
    if (x >= 0.f) return 1.f / (1.f + expf(-x));
    float e = expf(x); return e / (1.f + e);
}

__device__ void bitonic_desc(unsigned long long* a, int sz) {
    for (int k = 2; k <= sz; k <<= 1)
        for (int j = k >> 1; j > 0; j >>= 1) {
            for (int t = threadIdx.x; t < sz; t += blockDim.x) {
                int ixj = t ^ j;
                if (ixj > t) {
                    unsigned long long u = a[t], v = a[ixj];
                    bool sw = ((t & k) == 0) ? (u < v) : (u > v);
                    if (sw) { a[t] = v; a[ixj] = u; }
                }
            }
            __syncthreads();
        }
}

__global__ void k_zcnt() {
    if (threadIdx.x < NIMG * 3) g_cnt[threadIdx.x] = 0;
}

// one thread per 4 consecutive pixels; all index math constant-folded
template<int H, int W, int LVL, int CAPL, int LOFF>
__device__ __forceinline__ void score_body(const float* __restrict__ cls,
                                           const float* __restrict__ gau, int bid) {
    constexpr int hw  = H * W;
    constexpr int CHW = CCH * hw;
    constexpr int QPI = CHW / 4;
    int q   = bid * 256 + threadIdx.x;
    int n   = q / QPI;
    int pix = q * 4;
    int r   = pix - n * CHW;
    int pp  = r % hw;                 // hw is NOT a power of two
    int y   = pp / W;
    int x0  = pp & (W - 1);           // W IS a power of two

    float4 cl4 = *(const float4*)(cls + (size_t)pix);
    bool iy = (y > 0) & (y < H - 1);
    bool t0 = iy && (x0 > 0)     && (cl4.x > BOX_LOGIT_THRESH);
    bool t1 = iy &&                 (cl4.y > BOX_LOGIT_THRESH);
    bool t2 = iy &&                 (cl4.z > BOX_LOGIT_THRESH);
    bool t3 = iy && (x0 < W - 4) && (cl4.w > BOX_LOGIT_THRESH);

    unsigned sbv[4]; int rrv[4]; int cnt = 0;

    if (t0 | t1 | t2 | t3) {
        const float* G = gau + (size_t)(pix - pp);
        bool hasL = x0 > 0, hasR = x0 < W - 4;
        const float4* Gm = (const float4*)(G + pp - W);
        const float4* Gc = (const float4*)(G + pp);
        const float4* Gp = (const float4*)(G + pp + W);
        float4 z = make_float4(0.f, 0.f, 0.f, 0.f);
        float4 u0 = hasL ? Gm[-1] : z, u1 = Gm[0], u2 = hasR ? Gm[1] : z;
        float4 c0 = hasL ? Gc[-1] : z, c1 = Gc[0], c2 = hasR ? Gc[1] : z;
        float4 d0 = hasL ? Gp[-1] : z, d1 = Gp[0], d2 = hasR ? Gp[1] : z;

        if (t0) {
            float gc = c1.x;
            float m = fmaxf(fmaxf(u0.w, u1.x), u1.y);
            m = fmaxf(m, fmaxf(c0.w, c1.y));
            m = fmaxf(m, fmaxf(fmaxf(d0.w, d1.x), d1.y));
            if (gc >= m) {
                float sc = sqrtf(sigm(cl4.x) * sigm(gc));
                sbv[cnt] = __float_as_uint(sc); rrv[cnt] = r + 0; cnt++;
            }
        }
        if (t1) {
            float gc = c1.y;
            float m = fmaxf(fmaxf(u1.x, u1.y), u1.z);
            m = fmaxf(m, fmaxf(c1.x, c1.z));
            m = fmaxf(m, fmaxf(fmaxf(d1.x, d1.y), d1.z));
            if (gc >= m) {
                float sc = sqrtf(sigm(cl4.y) * sigm(gc));
                sbv[cnt] = __float_as_uint(sc); rrv[cnt] = r + 1; cnt++;
            }
        }
        if (t2) {
            float gc = c1.z;
            float m = fmaxf(fmaxf(u1.y, u1.z), u1.w);
            m = fmaxf(m, fmaxf(c1.y, c1.w));
            m = fmaxf(m, fmaxf(fmaxf(d1.y, d1.z), d1.w));
            if (gc >= m) {
                float sc = sqrtf(sigm(cl4.z) * sigm(gc));
                sbv[cnt] = __float_as_uint(sc); rrv[cnt] = r + 2; cnt++;
            }
        }
        if (t3) {
            float gc = c1.w;
            float m = fmaxf(fmaxf(u1.z, u1.w), u2.x);
            m = fmaxf(m, fmaxf(c1.z, c2.x));
            m = fmaxf(m, fmaxf(fmaxf(d1.z, d1.w), d2.x));
            if (gc >= m) {
                float sc = sqrtf(sigm(cl4.w) * sigm(gc));
                sbv[cnt] = __float_as_uint(sc); rrv[cnt] = r + 3; cnt++;
            }
        }
    }

    int lane = threadIdx.x & 31;
    unsigned cinc = (unsigned)cnt;
    #pragma unroll
    for (int off = 1; off < 32; off <<= 1) {
        unsigned t = __shfl_up_sync(0xFFFFFFFFu, cinc, off);
        if (lane >= off) cinc += t;
    }
    unsigned total = __shfl_sync(0xFFFFFFFFu, cinc, 31);
    if (total == 0u) return;
    int b = n * 3 + LVL;
    unsigned base = 0;
    if (lane == 0) base = atomicAdd(&g_cnt[b], total);
    base = __shfl_sync(0xFFFFFFFFu, base, 0);
    unsigned pre = cinc - (unsigned)cnt;
    #pragma unroll
    for (int k = 0; k < cnt; k++) {
        unsigned slot = base + pre + (unsigned)k;
        if (slot < (unsigned)CAPL)
            g_cand[(size_t)n * CAPI + LOFF + slot] =
                ((unsigned long long)sbv[k] << 32) | (unsigned)(~rrv[k]);
    }
}

__global__ void __launch_bounds__(256) k_score_all(
    const float* __restrict__ c0, const float* __restrict__ g0,
    const float* __restrict__ c1, const float* __restrict__ g1,
    const float* __restrict__ c2, const float* __restrict__ g2) {
    int bid = blockIdx.x;
    if (bid < 12800)       score_body<160,256,0,CAP0,0>        (c0, g0, bid);
    else if (bid < 16000)  score_body<80, 128,1,CAP1,CAP0>     (c1, g1, bid - 12800);
    else                   score_body<40, 64, 2,CAP2,CAP0+CAP1>(c2, g2, bid - 16000);
}

// top-500 select per (image, level): shared-mem 2-pass histogram + sort + fused solve
__global__ void __launch_bounds__(1024) k_select(const float* __restrict__ g0,
                                                 const float* __restrict__ g1,
                                                 const float* __restrict__ g2) {
    int b = blockIdx.x;
    int n = b / 3, lvl = b % 3;
    __shared__ unsigned int sh_c[1024];
    __shared__ unsigned int sh_f[256];
    __shared__ unsigned long long sel[4096];
    __shared__ unsigned int sT, sM, sAbove;
    __shared__ int sB;
    int tid = threadIdx.x;

    unsigned cnt = min(g_cnt[b], (unsigned)c_cap[lvl]);
    const unsigned long long* cand = &g_cand[(size_t)n * CAPI + c_loff[lvl]];

    sh_c[tid] = 0;
    if (tid == 0) { sM = 0; sB = -1; sAbove = 0; sT = 0; }
    __syncthreads();

    for (unsigned i = tid; i < cnt; i += 1024) {
        unsigned hi = (unsigned)(cand[i] >> 32);
        atomicAdd(&sh_c[hi >> 20], 1u);
    }
    __syncthreads();

    for (int off = 1; off < 1024; off <<= 1) {
        unsigned v = sh_c[tid];
        if (tid + off < 1024) v += sh_c[tid + off];
        __syncthreads();
        sh_c[tid] = v;
        __syncthreads();
    }
    if (sh_c[tid] >= TOPN && (tid == 1023 || sh_c[tid + 1] < TOPN)) {
        sB = tid;
        sAbove = (tid == 1023) ? 0u : sh_c[tid + 1];
    }
    if (tid < 256) sh_f[tid] = 0;
    __syncthreads();
    int B = sB;
    unsigned above = sAbove;

    if (B >= 0) {
        for (unsigned i = tid; i < cnt; i += 1024) {
            unsigned hi = (unsigned)(cand[i] >> 32);
            if ((int)(hi >> 20) == B) atomicAdd(&sh_f[(hi >> 12) & 255], 1u);
        }
    }
    __syncthreads();
    for (int off = 1; off < 256; off <<= 1) {
        unsigned v = 0;
        if (tid < 256) { v = sh_f[tid]; if (tid + off < 256) v += sh_f[tid + off]; }
        __syncthreads();
        if (tid < 256) sh_f[tid] = v;
        __syncthreads();
    }
    if (B >= 0 && tid < 256) {
        unsigned cum = above + sh_f[tid];
        unsigned nxt = (tid == 255) ? above : above + sh_f[tid + 1];
        if (cum >= TOPN && nxt < TOPN) sT = ((unsigned)B << 8) | (unsigned)tid;
    }
    __syncthreads();
    unsigned T = sT;

    for (unsigned i = tid; i < cnt; i += 1024) {
        unsigned long long k = cand[i];
        if ((unsigned)(k >> 44) >= T) {
            unsigned p = atomicAdd(&sM, 1u);
            if (p < 4096) sel[p] = k;
        }
    }
    __syncthreads();
    unsigned mM = min(sM, 4096u);
    for (int i = tid; i < 4096; i += 1024)
        if ((unsigned)i >= mM) sel[i] = 0ull;
    __syncthreads();
    bitonic_desc(sel, 4096);

    if (tid < TOPN) {
        int t = n * NCAND + lvl * TOPN + tid;
        unsigned long long key = sel[tid];
        g_top[t] = key;

        int H, W, step; const float* G;
        if (lvl == 0)      { H = 160; W = 256; step = 8;  G = g0; }
        else if (lvl == 1) { H = 80;  W = 128; step = 16; G = g1; }
        else               { H = 40;  W = 64;  step = 32; G = g2; }
        float sc = __uint_as_float((unsigned)(key >> 32));
        unsigned flat = ~(unsigned)key;
        int hw = H * W;
        if (!(sc > 0.f) || flat >= (unsigned)(CCH * hw)) {
            g_x1[t]=0.f; g_y1[t]=0.f; g_x2[t]=0.f; g_y2[t]=0.f; g_lb[t]=1; g_vd[t]=0;
        } else {
            int c = (int)(flat / hw);
            int rem = (int)(flat - (unsigned)c * hw);
            int y = rem / W, x = rem - y * W;
            const float* Bp = G + ((size_t)(n * CCH + c)) * hw;
            auto LV = [&](int yy, int xx) -> float {
                yy = min(max(yy, 0), H - 1);
                xx = min(max(xx, 0), W - 1);
                return log1pf(expf(-Bp[yy * W + xx])) * 0.125f;
            };
            float l0 = LV(y, x);
            float lxp = LV(y, x+1), lxm = LV(y, x-1);
            float lyp = LV(y+1, x), lym = LV(y-1, x);
            float Ax = (lxp + lxm - 2.f * l0) * 0.5f;
            float Ay = (lyp + lym - 2.f * l0) * 0.5f;
            bool px = Ax > 1e-8f, py = Ay > 1e-8f;
            float Axs = px ? Ax : 1.f, Ays = py ? Ay : 1.f;
            float mux = (float)x - (lxp - lxm) / (4.f * Axs);
            float muy = (float)y - (lyp - lym) / (4.f * Ays);
            float wb = (px ? rsqrtf(2.f * Axs) : 0.f) * (float)step;
            float hb = (py ? rsqrtf(2.f * Ays) : 0.f) * (float)step;
            float x1 = mux * (float)step - 0.5f * wb + (float)(step - 1) * 0.5f;
            float y1 = muy * (float)step - 0.5f * hb + (float)(step - 1) * 0.5f;
            bool vd = (wb > 0.f) && (hb > 0.f);
            float x2 = x1 + wb - 1.f, y2 = y1 + hb - 1.f;
            g_x1[t] = fminf(fmaxf(x1, 0.f), 2047.f);
            g_x2[t] = fminf(fmaxf(x2, 0.f), 2047.f);
            g_y1[t] = fminf(fmaxf(y1, 0.f), 1279.f);
            g_y2[t] = fminf(fmaxf(y2, 0.f), 1279.f);
            g_lb[t] = c + 1; g_vd[t] = vd ? 1 : 0;
        }
    }
}

// per-image NMS: sort, then EXACT per-class greedy (one warp per class)
__global__ void __launch_bounds__(1024) k_nms(float* __restrict__ out) {
    __shared__ unsigned long long skey[2048];
    __shared__ float bx1[NCAND], by1[NCAND], bx2[NCAND], by2[NCAND];
    __shared__ short slb[NCAND];
    __shared__ unsigned char keep[NCAND];
    __shared__ short cls_list[NCAND];
    __shared__ int   ofs[82];
    __shared__ int   s_ti[100];
    int n = blockIdx.x, tid = threadIdx.x;
    int w = tid >> 5, lane = tid & 31;

    for (int p = tid; p < 2048; p += 1024) {
        unsigned long long kk = 0ull;
        if (p < NCAND) {
            int gi = n * NCAND + p;
            float sc = __uint_as_float((unsigned)(g_top[gi] >> 32));
            float sv = g_vd[gi] ? sc : -1.f;
            unsigned bits = __float_as_uint(sv);
            unsigned ord = (bits & 0x80000000u) ? ~bits : (bits | 0x80000000u);
            kk = ((unsigned long long)ord << 32) | (0xFFFFFFFFu - (unsigned)p);
        }
        skey[p] = kk;
    }
    __syncthreads();
    bitonic_desc(skey, 2048);

    for (int p = tid; p < NCAND; p += 1024) {
        int pos = (int)(0xFFFFFFFFu - (unsigned)skey[p]);
        int gi = n * NCAND + pos;
        bx1[p]=g_x1[gi]; by1[p]=g_y1[gi]; bx2[p]=g_x2[gi]; by2[p]=g_y2[gi];
        slb[p]=(short)g_lb[gi]; keep[p]=g_vd[gi];
    }
    if (tid < 82) ofs[tid] = 0;
    __syncthreads();

    // count VALID boxes per class (invalid never suppress and stay keep=0)
    for (int p = tid; p < NCAND; p += 1024)
        if (keep[p]) atomicAdd((unsigned*)&ofs[slb[p]], 1u);
    __syncthreads();
    if (tid == 0) {
        int acc = 0;
        for (int c = 1; c <= 80; c++) { int v = ofs[c]; ofs[c] = acc; acc += v; }
        ofs[81] = acc;
        ofs[0]  = 0;
    }
    __syncthreads();

    // stable scatter: warp w owns labels w+1, w+33, w+65
    for (int lbl = w + 1; lbl <= 80; lbl += 32) {
        int start = ofs[lbl];
        int fill = 0;
        for (int base = 0; base < NCAND; base += 32) {
            int p = base + lane;
            bool match = (p < NCAND) && keep[p] && (slb[p] == (short)lbl);
            unsigned bal = __ballot_sync(0xFFFFFFFFu, match);
            if (match) {
                int pre = __popc(bal & ((1u << lane) - 1u));
                cls_list[start + fill + pre] = (short)p;
            }
            fill += __popc(bal);
        }
    }
    __syncthreads();

    // per-class exact greedy NMS (warp-local, no block syncs)
    for (int lbl = w + 1; lbl <= 80; lbl += 32) {
        int start = ofs[lbl];
        int k = ofs[lbl + 1] - start;
        if (k < 2) continue;
        for (int t0 = 0; t0 < k; t0 += 32) {
            int e = t0 + lane;
            bool in = e < k;
            int idx = in ? (int)cls_list[start + e] : 0;
            float x1 = 0, y1 = 0, x2 = 0, y2 = 0, ar = 1.f;
            bool alive = false;
            if (in) {
                x1 = bx1[idx]; y1 = by1[idx]; x2 = bx2[idx]; y2 = by2[idx];
                ar = (x2 - x1 + 1.f) * (y2 - y1 + 1.f);
                alive = keep[idx] != 0;
            }
            if (alive) {
                for (int qe = 0; qe < t0; qe++) {
                    int qi = (int)cls_list[start + qe];
                    if (!keep[qi]) continue;
                    float qx1 = bx1[qi], qy1 = by1[qi], qx2 = bx2[qi], qy2 = by2[qi];
                    float iw = fmaxf(fminf(x2, qx2) - fmaxf(x1, qx1) + 1.f, 0.f);
                    float ih = fmaxf(fminf(y2, qy2) - fmaxf(y1, qy1) + 1.f, 0.f);
                    float inter = iw * ih;
                    float qar = (qx2 - qx1 + 1.f) * (qy2 - qy1 + 1.f);
                    if (inter / (ar + qar - inter + 1e-9f) > 0.5f) { alive = false; break; }
                }
            }
            int lim = min(32, k - t0);
            unsigned sup = 0;
            for (int m = 0; m < lim - 1; m++) {
                float mx1 = __shfl_sync(0xFFFFFFFFu, x1, m);
                float my1 = __shfl_sync(0xFFFFFFFFu, y1, m);
                float mx2 = __shfl_sync(0xFFFFFFFFu, x2, m);
                float my2 = __shfl_sync(0xFFFFFFFFu, y2, m);
                float mar = __shfl_sync(0xFFFFFFFFu, ar, m);
                if (in && m < lane) {
                    float iw = fmaxf(fminf(x2, mx2) - fmaxf(x1, mx1) + 1.f, 0.f);
                    float ih = fmaxf(fminf(y2, my2) - fmaxf(y1, my1) + 1.f, 0.f);
                    float inter = iw * ih;
                    if (inter / (ar + mar - inter + 1e-9f) > 0.5f) sup |= (1u << m);
                }
            }
            for (int m = 0; m < lim - 1; m++) {
                unsigned bal = __ballot_sync(0xFFFFFFFFu, alive);
                if (lane > m && ((bal >> m) & 1u) && ((sup >> m) & 1u)) alive = false;
            }
            if (in) keep[idx] = alive ? 1 : 0;
        }
    }
    __syncthreads();

    if (tid < 32) {
        int cnt = 0;
        for (int pass = 0; pass < 2; pass++) {
            for (int b2 = 0; b2 < NCAND && cnt < 100; b2 += 32) {
                int i2 = b2 + lane;
                bool pr = (i2 < NCAND) && ((pass == 0) ? (keep[i2] != 0) : (keep[i2] == 0));
                unsigned ww = __ballot_sync(0xFFFFFFFFu, pr);
                int pre = __popc(ww & ((1u << lane) - 1u));
                if (pr && cnt + pre < 100) s_ti[cnt + pre] = i2;
                cnt += __popc(ww);
            }
            if (cnt > 100) cnt = 100;
        }
    }
    __syncthreads();

    if (tid < 100) {
        int p = s_ti[tid];
        unsigned ord = (unsigned)(skey[p] >> 32);
        float s = (ord & 0x80000000u) ? __uint_as_float(ord ^ 0x80000000u)
                                      : __uint_as_float(~ord);
        float tv = keep[p] ? s : -1.f;
        out[n*400 + tid*4 + 0] = bx1[p];
        out[n*400 + tid*4 + 1] = by1[p];
        out[n*400 + tid*4 + 2] = bx2[p];
        out[n*400 + tid*4 + 3] = by2[p];
        out[1600 + n*100 + tid] = tv;
        out[2000 + n*100 + tid] = (float)slb[p];
        out[2400 + n*100 + tid] = (tv > 0.f) ? 1.f : 0.f;
    }
}

extern "C" void kernel_launch(void* const* d_in, const int* in_sizes, int n_in,
                              void* d_out, int out_size) {
    const float *cls[3], *gau[3];
    if (in_sizes[0] == in_sizes[1]) {          // interleaved
        cls[0]=(const float*)d_in[0]; gau[0]=(const float*)d_in[1];
        cls[1]=(const float*)d_in[2]; gau[1]=(const float*)d_in[3];
        cls[2]=(const float*)d_in[4]; gau[2]=(const float*)d_in[5];
    } else {                                   // grouped
        cls[0]=(const float*)d_in[0]; cls[1]=(const float*)d_in[1]; cls[2]=(const float*)d_in[2];
        gau[0]=(const float*)d_in[3]; gau[1]=(const float*)d_in[4]; gau[2]=(const float*)d_in[5];
    }
    float* out = (float*)d_out;

    k_zcnt<<<1, 32>>>();
    k_score_all<<<16800, 256>>>(cls[0], gau[0], cls[1], gau[1], cls[2], gau[2]);
    k_select<<<NIMG * 3, 1024>>>(gau[0], gau[1], gau[2]);
    k_nms<<<NIMG, 1024>>>(out);
}

// round 10
// speedup vs baseline: 6.6727x; 1.1446x over previous
#include <cuda_runtime.h>
#include <cstdint>

#define NIMG  4
#define CCH   80
#define TOPN  500
#define NCAND 1500
#define CAP0 524288
#define CAP1 131072
#define CAP2 65536
#define CAPI (CAP0+CAP1+CAP2)
#define BOX_LOGIT_THRESH (-2.9444389791664403f)

__device__ unsigned long long g_cand[NIMG * CAPI];
__device__ unsigned int       g_cnt[NIMG * 3];
__device__ unsigned long long g_top[NIMG * NCAND];
__device__ float g_x1[NIMG*NCAND], g_y1[NIMG*NCAND], g_x2[NIMG*NCAND], g_y2[NIMG*NCAND];
__device__ int   g_lb[NIMG*NCAND];
__device__ unsigned char g_vd[NIMG*NCAND];

__constant__ int c_cap[3]  = {CAP0, CAP1, CAP2};
__constant__ int c_loff[3] = {0, CAP0, CAP0 + CAP1};

__device__ __forceinline__ float sigm(float x) {
    if (x >= 0.f) return 1.f / (1.f + expf(-x));
    float e = expf(x); return e / (1.f + e);
}

// hybrid bitonic descending sort, SZ elements, 1024 threads.
// j<32 phases in registers via shfl_xor; j>=32 via smem + barrier.
template<int SZ>
__device__ void bitonic_desc_h(unsigned long long* a) {
    constexpr int E = SZ / 1024;
    int tid = threadIdx.x;
    unsigned long long v[E];
    #pragma unroll
    for (int m = 0; m < E; m++) v[m] = a[tid + (m << 10)];
    // k = 2..32 entirely in registers
    #pragma unroll
    for (int k = 2; k <= 32; k <<= 1) {
        #pragma unroll
        for (int j = k >> 1; j >= 1; j >>= 1) {
            #pragma unroll
            for (int m = 0; m < E; m++) {
                int t = tid + (m << 10);
                unsigned long long pv = __shfl_xor_sync(0xFFFFFFFFu, v[m], j);
                bool keepmax = (((t & k) == 0) == ((t & j) == 0));
                bool pmax = pv > v[m];
                if (keepmax == pmax) v[m] = pv;
            }
        }
    }
    #pragma unroll
    for (int m = 0; m < E; m++) a[tid + (m << 10)] = v[m];
    __syncthreads();
    for (int k = 64; k <= SZ; k <<= 1) {
        for (int j = k >> 1; j >= 32; j >>= 1) {
            #pragma unroll
            for (int m = 0; m < E; m++) {
                int t = tid + (m << 10);
                int ixj = t ^ j;
                if (ixj > t) {
                    unsigned long long u = a[t], w = a[ixj];
                    bool sw = ((t & k) == 0) ? (u < w) : (u > w);
                    if (sw) { a[t] = w; a[ixj] = u; }
                }
            }
            __syncthreads();
        }
        #pragma unroll
        for (int m = 0; m < E; m++) v[m] = a[tid + (m << 10)];
        #pragma unroll
        for (int j = 16; j >= 1; j >>= 1) {
            #pragma unroll
            for (int m = 0; m < E; m++) {
                int t = tid + (m << 10);
                unsigned long long pv = __shfl_xor_sync(0xFFFFFFFFu, v[m], j);
                bool keepmax = (((t & k) == 0) == ((t & j) == 0));
                bool pmax = pv > v[m];
                if (keepmax == pmax) v[m] = pv;
            }
        }
        #pragma unroll
        for (int m = 0; m < E; m++) a[tid + (m << 10)] = v[m];
        __syncthreads();
    }
}

// shared helper: evaluate quad stencil + emit candidates (warp-aggregated)
template<int LVL, int CAPL, int LOFF>
__device__ __forceinline__ void emit_candidates(int n, unsigned* sbv, int* rrv, int cnt) {
    int lane = threadIdx.x & 31;
    unsigned cinc = (unsigned)cnt;
    #pragma unroll
    for (int off = 1; off < 32; off <<= 1) {
        unsigned t = __shfl_up_sync(0xFFFFFFFFu, cinc, off);
        if (lane >= off) cinc += t;
    }
    unsigned total = __shfl_sync(0xFFFFFFFFu, cinc, 31);
    if (total == 0u) return;
    int b = n * 3 + LVL;
    unsigned base = 0;
    if (lane == 0) base = atomicAdd(&g_cnt[b], total);
    base = __shfl_sync(0xFFFFFFFFu, base, 0);
    unsigned pre = cinc - (unsigned)cnt;
    #pragma unroll
    for (int k = 0; k < 4; k++) {
        if (k >= cnt) break;
        unsigned slot = base + pre + (unsigned)k;
        if (slot < (unsigned)CAPL)
            g_cand[(size_t)n * CAPI + LOFF + slot] =
                ((unsigned long long)sbv[k] << 32) | (unsigned)(~rrv[k]);
    }
}

// 9-point window evaluation on 3 float4-rows
#define EVAL_QUAD(cl, gc, A, Bq, Cq) do {                                   \
    float m = fmaxf(fmaxf(A, Bq), Cq);                                      \
    if (gc >= m) {                                                          \
        float sc = sqrtf(sigm(cl) * sigm(gc));                              \
        sbv[cnt] = __float_as_uint(sc); rrv[cnt] = rb + qk; cnt++;          \
    }                                                                       \
} while (0)

// tiled score: each block owns R rows of one (image,channel); gau rows staged in smem
template<int H, int W, int R, int LVL, int CAPL, int LOFF>
__device__ __forceinline__ void score_tile(const float* __restrict__ cls,
                                           const float* __restrict__ gau,
                                           float* sg, int bid) {
    constexpr int hw  = H * W;
    constexpr int RPC = H / R;             // row-blocks per channel
    constexpr int w4  = W / 4;
    int tid = threadIdx.x;
    int cb  = bid / RPC;                   // image*channel index
    int ry  = (bid - cb * RPC) * R;
    int n   = cb / CCH;
    size_t base = (size_t)cb * hw;

    // stage rows ry-1 .. ry+R (clamped) of gau channel into smem
    constexpr int NF4 = (R + 2) * w4;
    for (int i = tid; i < NF4; i += 256) {
        int row = i / w4;
        int c4  = i - row * w4;
        int gy  = min(max(ry - 1 + row, 0), H - 1);
        ((float4*)sg)[i] = *(const float4*)(gau + base + (size_t)gy * W + c4 * 4);
    }
    __syncthreads();

    int t  = tid * 4;
    int lr = t / W;
    int x0 = t - lr * W;
    int y  = ry + lr;
    int sr = lr + 1;

    float4 cl4 = *(const float4*)(cls + base + (size_t)y * W + x0);
    bool iy = (y > 0) & (y < H - 1);
    bool t0 = iy && (x0 > 0)     && (cl4.x > BOX_LOGIT_THRESH);
    bool t1 = iy &&                 (cl4.y > BOX_LOGIT_THRESH);
    bool t2 = iy &&                 (cl4.z > BOX_LOGIT_THRESH);
    bool t3 = iy && (x0 < W - 4) && (cl4.w > BOX_LOGIT_THRESH);

    unsigned sbv[4]; int rrv[4]; int cnt = 0;
    int rb = (cb - n * CCH) * hw + y * W + x0;  // r of col x0

    if (t0 | t1 | t2 | t3) {
        bool hasL = x0 > 0, hasR = x0 < W - 4;
        const float4* Sm = (const float4*)(sg + (sr - 1) * W + x0);
        const float4* Sc = (const float4*)(sg + sr * W + x0);
        const float4* Sp = (const float4*)(sg + (sr + 1) * W + x0);
        float4 z = make_float4(0.f, 0.f, 0.f, 0.f);
        float4 u0 = hasL ? Sm[-1] : z, u1 = Sm[0], u2 = hasR ? Sm[1] : z;
        float4 c0 = hasL ? Sc[-1] : z, c1 = Sc[0], c2 = hasR ? Sc[1] : z;
        float4 d0 = hasL ? Sp[-1] : z, d1 = Sp[0], d2 = hasR ? Sp[1] : z;

        if (t0) { int qk = 0;
            EVAL_QUAD(cl4.x, c1.x,
                fmaxf(fmaxf(u0.w, u1.x), u1.y),
                fmaxf(c0.w, c1.y),
                fmaxf(fmaxf(d0.w, d1.x), d1.y)); }
        if (t1) { int qk = 1;
            EVAL_QUAD(cl4.y, c1.y,
                fmaxf(fmaxf(u1.x, u1.y), u1.z),
                fmaxf(c1.x, c1.z),
                fmaxf(fmaxf(d1.x, d1.y), d1.z)); }
        if (t2) { int qk = 2;
            EVAL_QUAD(cl4.z, c1.z,
                fmaxf(fmaxf(u1.y, u1.z), u1.w),
                fmaxf(c1.y, c1.w),
                fmaxf(fmaxf(d1.y, d1.z), d1.w)); }
        if (t3) { int qk = 3;
            EVAL_QUAD(cl4.w, c1.w,
                fmaxf(fmaxf(u1.z, u1.w), u2.x),
                fmaxf(c1.z, c2.x),
                fmaxf(fmaxf(d1.z, d1.w), d2.x)); }
    }
    emit_candidates<LVL, CAPL, LOFF>(n, sbv, rrv, cnt);
}

// old untiled path (level 2 only: hw doesn't divide into 1024-px row blocks)
template<int H, int W, int LVL, int CAPL, int LOFF>
__device__ __forceinline__ void score_body(const float* __restrict__ cls,
                                           const float* __restrict__ gau, int bid) {
    constexpr int hw  = H * W;
    constexpr int CHW = CCH * hw;
    constexpr int QPI = CHW / 4;
    int q   = bid * 256 + threadIdx.x;
    int n   = q / QPI;
    int pix = q * 4;
    int r   = pix - n * CHW;
    int pp  = r % hw;
    int y   = pp / W;
    int x0  = pp & (W - 1);

    float4 cl4 = *(const float4*)(cls + (size_t)pix);
    bool iy = (y > 0) & (y < H - 1);
    bool t0 = iy && (x0 > 0)     && (cl4.x > BOX_LOGIT_THRESH);
    bool t1 = iy &&                 (cl4.y > BOX_LOGIT_THRESH);
    bool t2 = iy &&                 (cl4.z > BOX_LOGIT_THRESH);
    bool t3 = iy && (x0 < W - 4) && (cl4.w > BOX_LOGIT_THRESH);

    unsigned sbv[4]; int rrv[4]; int cnt = 0;
    int rb = r;

    if (t0 | t1 | t2 | t3) {
        const float* G = gau + (size_t)(pix - pp);
        bool hasL = x0 > 0, hasR = x0 < W - 4;
        const float4* Gm = (const float4*)(G + pp - W);
        const float4* Gc = (const float4*)(G + pp);
        const float4* Gp = (const float4*)(G + pp + W);
        float4 z = make_float4(0.f, 0.f, 0.f, 0.f);
        float4 u0 = hasL ? Gm[-1] : z, u1 = Gm[0], u2 = hasR ? Gm[1] : z;
        float4 c0 = hasL ? Gc[-1] : z, c1 = Gc[0], c2 = hasR ? Gc[1] : z;
        float4 d0 = hasL ? Gp[-1] : z, d1 = Gp[0], d2 = hasR ? Gp[1] : z;

        if (t0) { int qk = 0;
            EVAL_QUAD(cl4.x, c1.x,
                fmaxf(fmaxf(u0.w, u1.x), u1.y),
                fmaxf(c0.w, c1.y),
                fmaxf(fmaxf(d0.w, d1.x), d1.y)); }
        if (t1) { int qk = 1;
            EVAL_QUAD(cl4.y, c1.y,
                fmaxf(fmaxf(u1.x, u1.y), u1.z),
                fmaxf(c1.x, c1.z),
                fmaxf(fmaxf(d1.x, d1.y), d1.z)); }
        if (t2) { int qk = 2;
            EVAL_QUAD(cl4.z, c1.z,
                fmaxf(fmaxf(u1.y, u1.z), u1.w),
                fmaxf(c1.y, c1.w),
                fmaxf(fmaxf(d1.y, d1.z), d1.w)); }
        if (t3) { int qk = 3;
            EVAL_QUAD(cl4.w, c1.w,
                fmaxf(fmaxf(u1.z, u1.w), u2.x),
                fmaxf(c1.z, c2.x),
                fmaxf(fmaxf(d1.z, d1.w), d2.x)); }
    }
    emit_candidates<LVL, CAPL, LOFF>(n, sbv, rrv, cnt);
}

__global__ void __launch_bounds__(256) k_score_all(
    const float* __restrict__ c0, const float* __restrict__ g0,
    const float* __restrict__ c1, const float* __restrict__ g1,
    const float* __restrict__ c2, const float* __restrict__ g2) {
    __shared__ __align__(16) float sg[6 * 256];   // lvl0: 6x256, lvl1: 10x128
    int bid = blockIdx.x;
    if (bid < 12800)       score_tile<160,256,4,0,CAP0,0>   (c0, g0, sg, bid);
    else if (bid < 16000)  score_tile<80, 128,8,1,CAP1,CAP0>(c1, g1, sg, bid - 12800);
    else                   score_body<40, 64, 2,CAP2,CAP0+CAP1>(c2, g2, bid - 16000);
}

// top-500 select per (image, level): smem 2-pass histogram + hybrid sort + fused solve
__global__ void __launch_bounds__(1024) k_select(const float* __restrict__ g0,
                                                 const float* __restrict__ g1,
                                                 const float* __restrict__ g2) {
    int b = blockIdx.x;
    int n = b / 3, lvl = b % 3;
    __shared__ unsigned int sh_c[1024];
    __shared__ unsigned int sh_f[256];
    __shared__ unsigned long long sel[4096];
    __shared__ unsigned int sT, sM, sAbove;
    __shared__ int sB;
    int tid = threadIdx.x;

    unsigned cnt = min(g_cnt[b], (unsigned)c_cap[lvl]);
    const unsigned long long* cand = &g_cand[(size_t)n * CAPI + c_loff[lvl]];

    sh_c[tid] = 0;
    if (tid == 0) { sM = 0; sB = -1; sAbove = 0; sT = 0; g_cnt[b] = 0; }  // reset for next replay
    __syncthreads();

    for (unsigned i = tid; i < cnt; i += 1024) {
        unsigned hi = (unsigned)(cand[i] >> 32);
        atomicAdd(&sh_c[hi >> 20], 1u);
    }
    __syncthreads();

    for (int off = 1; off < 1024; off <<= 1) {
        unsigned v = sh_c[tid];
        if (tid + off < 1024) v += sh_c[tid + off];
        __syncthreads();
        sh_c[tid] = v;
        __syncthreads();
    }
    if (sh_c[tid] >= TOPN && (tid == 1023 || sh_c[tid + 1] < TOPN)) {
        sB = tid;
        sAbove = (tid == 1023) ? 0u : sh_c[tid + 1];
    }
    if (tid < 256) sh_f[tid] = 0;
    __syncthreads();
    int B = sB;
    unsigned above = sAbove;

    if (B >= 0) {
        for (unsigned i = tid; i < cnt; i += 1024) {
            unsigned hi = (unsigned)(cand[i] >> 32);
            if ((int)(hi >> 20) == B) atomicAdd(&sh_f[(hi >> 12) & 255], 1u);
        }
    }
    __syncthreads();
    for (int off = 1; off < 256; off <<= 1) {
        unsigned v = 0;
        if (tid < 256) { v = sh_f[tid]; if (tid + off < 256) v += sh_f[tid + off]; }
        __syncthreads();
        if (tid < 256) sh_f[tid] = v;
        __syncthreads();
    }
    if (B >= 0 && tid < 256) {
        unsigned cum = above + sh_f[tid];
        unsigned nxt = (tid == 255) ? above : above + sh_f[tid + 1];
        if (cum >= TOPN && nxt < TOPN) sT = ((unsigned)B << 8) | (unsigned)tid;
    }
    __syncthreads();
    unsigned T = sT;

    for (unsigned i = tid; i < cnt; i += 1024) {
        unsigned long long k = cand[i];
        if ((unsigned)(k >> 44) >= T) {
            unsigned p = atomicAdd(&sM, 1u);
            if (p < 4096) sel[p] = k;
        }
    }
    __syncthreads();
    unsigned mM = min(sM, 4096u);
    for (int i = tid; i < 4096; i += 1024)
        if ((unsigned)i >= mM) sel[i] = 0ull;
    __syncthreads();
    bitonic_desc_h<4096>(sel);

    if (tid < TOPN) {
        int t = n * NCAND + lvl * TOPN + tid;
        unsigned long long key = sel[tid];
        g_top[t] = key;

        int H, W, step; const float* G;
        if (lvl == 0)      { H = 160; W = 256; step = 8;  G = g0; }
        else if (lvl == 1) { H = 80;  W = 128; step = 16; G = g1; }
        else               { H = 40;  W = 64;  step = 32; G = g2; }
        float sc = __uint_as_float((unsigned)(key >> 32));
        unsigned flat = ~(unsigned)key;
        int hw = H * W;
        if (!(sc > 0.f) || flat >= (unsigned)(CCH * hw)) {
            g_x1[t]=0.f; g_y1[t]=0.f; g_x2[t]=0.f; g_y2[t]=0.f; g_lb[t]=1; g_vd[t]=0;
        } else {
            int c = (int)(flat / hw);
            int rem = (int)(flat - (unsigned)c * hw);
            int y = rem / W, x = rem - y * W;
            const float* Bp = G + ((size_t)(n * CCH + c)) * hw;
            auto LV = [&](int yy, int xx) -> float {
                yy = min(max(yy, 0), H - 1);
                xx = min(max(xx, 0), W - 1);
                return log1pf(expf(-Bp[yy * W + xx])) * 0.125f;
            };
            float l0 = LV(y, x);
            float lxp = LV(y, x+1), lxm = LV(y, x-1);
            float lyp = LV(y+1, x), lym = LV(y-1, x);
            float Ax = (lxp + lxm - 2.f * l0) * 0.5f;
            float Ay = (lyp + lym - 2.f * l0) * 0.5f;
            bool px = Ax > 1e-8f, py = Ay > 1e-8f;
            float Axs = px ? Ax : 1.f, Ays = py ? Ay : 1.f;
            float mux = (float)x - (lxp - lxm) / (4.f * Axs);
            float muy = (float)y - (lyp - lym) / (4.f * Ays);
            float wb = (px ? rsqrtf(2.f * Axs) : 0.f) * (float)step;
            float hb = (py ? rsqrtf(2.f * Ays) : 0.f) * (float)step;
            float x1 = mux * (float)step - 0.5f * wb + (float)(step - 1) * 0.5f;
            float y1 = muy * (float)step - 0.5f * hb + (float)(step - 1) * 0.5f;
            bool vd = (wb > 0.f) && (hb > 0.f);
            float x2 = x1 + wb - 1.f, y2 = y1 + hb - 1.f;
            g_x1[t] = fminf(fmaxf(x1, 0.f), 2047.f);
            g_x2[t] = fminf(fmaxf(x2, 0.f), 2047.f);
            g_y1[t] = fminf(fmaxf(y1, 0.f), 1279.f);
            g_y2[t] = fminf(fmaxf(y2, 0.f), 1279.f);
            g_lb[t] = c + 1; g_vd[t] = vd ? 1 : 0;
        }
    }
}

// per-image NMS: hybrid sort, then exact per-class greedy (one warp per class)
__global__ void __launch_bounds__(1024) k_nms(float* __restrict__ out) {
    __shared__ unsigned long long skey[2048];
    __shared__ float bx1[NCAND], by1[NCAND], bx2[NCAND], by2[NCAND];
    __shared__ short slb[NCAND];
    __shared__ unsigned char keep[NCAND];
    __shared__ short cls_list[NCAND];
    __shared__ int   ofs[82];
    __shared__ int   s_ti[100];
    int n = blockIdx.x, tid = threadIdx.x;
    int w = tid >> 5, lane = tid & 31;

    for (int p = tid; p < 2048; p += 1024) {
        unsigned long long kk = 0ull;
        if (p < NCAND) {
            int gi = n * NCAND + p;
            float sc = __uint_as_float((unsigned)(g_top[gi] >> 32));
            float sv = g_vd[gi] ? sc : -1.f;
            unsigned bits = __float_as_uint(sv);
            unsigned ord = (bits & 0x80000000u) ? ~bits : (bits | 0x80000000u);
            kk = ((unsigned long long)ord << 32) | (0xFFFFFFFFu - (unsigned)p);
        }
        skey[p] = kk;
    }
    __syncthreads();
    bitonic_desc_h<2048>(skey);

    for (int p = tid; p < NCAND; p += 1024) {
        int pos = (int)(0xFFFFFFFFu - (unsigned)skey[p]);
        int gi = n * NCAND + pos;
        bx1[p]=g_x1[gi]; by1[p]=g_y1[gi]; bx2[p]=g_x2[gi]; by2[p]=g_y2[gi];
        slb[p]=(short)g_lb[gi]; keep[p]=g_vd[gi];
    }
    if (tid < 82) ofs[tid] = 0;
    __syncthreads();

    for (int p = tid; p < NCAND; p += 1024)
        if (keep[p]) atomicAdd((unsigned*)&ofs[slb[p]], 1u);
    __syncthreads();
    if (tid == 0) {
        int acc = 0;
        for (int c = 1; c <= 80; c++) { int v = ofs[c]; ofs[c] = acc; acc += v; }
        ofs[81] = acc;
        ofs[0]  = 0;
    }
    __syncthreads();

    // stable scatter: warp w owns labels w+1, w+33, w+65
    for (int lbl = w + 1; lbl <= 80; lbl += 32) {
        int start = ofs[lbl];
        int fill = 0;
        for (int base = 0; base < NCAND; base += 32) {
            int p = base + lane;
            bool match = (p < NCAND) && keep[p] && (slb[p] == (short)lbl);
            unsigned bal = __ballot_sync(0xFFFFFFFFu, match);
            if (match) {
                int pre = __popc(bal & ((1u << lane) - 1u));
                cls_list[start + fill + pre] = (short)p;
            }
            fill += __popc(bal);
        }
    }
    __syncthreads();

    // per-class exact greedy NMS (warp-local)
    for (int lbl = w + 1; lbl <= 80; lbl += 32) {
        int start = ofs[lbl];
        int k = ofs[lbl + 1] - start;
        if (k < 2) continue;
        for (int t0 = 0; t0 < k; t0 += 32) {
            int e = t0 + lane;
            bool in = e < k;
            int idx = in ? (int)cls_list[start + e] : 0;
            float x1 = 0, y1 = 0, x2 = 0, y2 = 0, ar = 1.f;
            bool alive = false;
            if (in) {
                x1 = bx1[idx]; y1 = by1[idx]; x2 = bx2[idx]; y2 = by2[idx];
                ar = (x2 - x1 + 1.f) * (y2 - y1 + 1.f);
                alive = keep[idx] != 0;
            }
            if (alive) {
                for (int qe = 0; qe < t0; qe++) {
                    int qi = (int)cls_list[start + qe];
                    if (!keep[qi]) continue;
                    float qx1 = bx1[qi], qy1 = by1[qi], qx2 = bx2[qi], qy2 = by2[qi];
                    float iw = fmaxf(fminf(x2, qx2) - fmaxf(x1, qx1) + 1.f, 0.f);
                    float ih = fmaxf(fminf(y2, qy2) - fmaxf(y1, qy1) + 1.f, 0.f);
                    float inter = iw * ih;
                    float qar = (qx2 - qx1 + 1.f) * (qy2 - qy1 + 1.f);
                    if (inter / (ar + qar - inter + 1e-9f) > 0.5f) { alive = false; break; }
                }
            }
            int lim = min(32, k - t0);
            unsigned sup = 0;
            for (int m = 0; m < lim - 1; m++) {
                float mx1 = __shfl_sync(0xFFFFFFFFu, x1, m);
                float my1 = __shfl_sync(0xFFFFFFFFu, y1, m);
                float mx2 = __shfl_sync(0xFFFFFFFFu, x2, m);
                float my2 = __shfl_sync(0xFFFFFFFFu, y2, m);
                float mar = __shfl_sync(0xFFFFFFFFu, ar, m);
                if (in && m < lane) {
                    float iw = fmaxf(fminf(x2, mx2) - fmaxf(x1, mx1) + 1.f, 0.f);
                    float ih = fmaxf(fminf(y2, my2) - fmaxf(y1, my1) + 1.f, 0.f);
                    float inter = iw * ih;
                    if (inter / (ar + mar - inter + 1e-9f) > 0.5f) sup |= (1u << m);
                }
            }
            for (int m = 0; m < lim - 1; m++) {
                unsigned bal = __ballot_sync(0xFFFFFFFFu, alive);
                if (lane > m && ((bal >> m) & 1u) && ((sup >> m) & 1u)) alive = false;
            }
            if (in) keep[idx] = alive ? 1 : 0;
        }
    }
    __syncthreads();

    if (tid < 32) {
        int cnt = 0;
        for (int pass = 0; pass < 2; pass++) {
            for (int b2 = 0; b2 < NCAND && cnt < 100; b2 += 32) {
                int i2 = b2 + lane;
                bool pr = (i2 < NCAND) && ((pass == 0) ? (keep[i2] != 0) : (keep[i2] == 0));
                unsigned ww = __ballot_sync(0xFFFFFFFFu, pr);
                int pre = __popc(ww & ((1u << lane) - 1u));
                if (pr && cnt + pre < 100) s_ti[cnt + pre] = i2;
                cnt += __popc(ww);
            }
            if (cnt > 100) cnt = 100;
        }
    }
    __syncthreads();

    if (tid < 100) {
        int p = s_ti[tid];
        unsigned ord = (unsigned)(skey[p] >> 32);
        float s = (ord & 0x80000000u) ? __uint_as_float(ord ^ 0x80000000u)
                                      : __uint_as_float(~ord);
        float tv = keep[p] ? s : -1.f;
        out[n*400 + tid*4 + 0] = bx1[p];
        out[n*400 + tid*4 + 1] = by1[p];
        out[n*400 + tid*4 + 2] = bx2[p];
        out[n*400 + tid*4 + 3] = by2[p];
        out[1600 + n*100 + tid] = tv;
        out[2000 + n*100 + tid] = (float)slb[p];
        out[2400 + n*100 + tid] = (tv > 0.f) ? 1.f : 0.f;
    }
}

extern "C" void kernel_launch(void* const* d_in, const int* in_sizes, int n_in,
                              void* d_out, int out_size) {
    const float *cls[3], *gau[3];
    if (in_sizes[0] == in_sizes[1]) {          // interleaved
        cls[0]=(const float*)d_in[0]; gau[0]=(const float*)d_in[1];
        cls[1]=(const float*)d_in[2]; gau[1]=(const float*)d_in[3];
        cls[2]=(const float*)d_in[4]; gau[2]=(const float*)d_in[5];
    } else {                                   // grouped
        cls[0]=(const float*)d_in[0]; cls[1]=(const float*)d_in[1]; cls[2]=(const float*)d_in[2];
        gau[0]=(const float*)d_in[3]; gau[1]=(const float*)d_in[4]; gau[2]=(const float*)d_in[5];
    }
    float* out = (float*)d_out;

    k_score_all<<<16800, 256>>>(cls[0], gau[0], cls[1], gau[1], cls[2], gau[2]);
    k_select<<<NIMG * 3, 1024>>>(gau[0], gau[1], gau[2]);
    k_nms<<<NIMG, 1024>>>(out);
}

// round 11
// speedup vs baseline: 7.2164x; 1.0815x over previous
#include <cuda_runtime.h>
#include <cstdint>

#define NIMG  4
#define CCH   80
#define TOPN  500
#define NCAND 1500
#define CAP0 524288
#define CAP1 131072
#define CAP2 65536
#define CAPI (CAP0+CAP1+CAP2)
#define BOX_LOGIT_THRESH (-2.9444389791664403f)

__device__ __align__(16) unsigned long long g_cand[NIMG * CAPI];
__device__ unsigned int       g_cnt[NIMG * 3];
__device__ unsigned long long g_top[NIMG * NCAND];
__device__ float g_x1[NIMG*NCAND], g_y1[NIMG*NCAND], g_x2[NIMG*NCAND], g_y2[NIMG*NCAND];
__device__ int   g_lb[NIMG*NCAND];
__device__ unsigned char g_vd[NIMG*NCAND];

__constant__ int c_cap[3]  = {CAP0, CAP1, CAP2};
__constant__ int c_loff[3] = {0, CAP0, CAP0 + CAP1};

__device__ __forceinline__ float sigm(float x) {
    if (x >= 0.f) return 1.f / (1.f + expf(-x));
    float e = expf(x); return e / (1.f + e);
}

// hybrid bitonic descending sort, SZ elements, 1024 threads.
template<int SZ>
__device__ void bitonic_desc_h(unsigned long long* a) {
    constexpr int E = SZ / 1024;
    int tid = threadIdx.x;
    unsigned long long v[E];
    #pragma unroll
    for (int m = 0; m < E; m++) v[m] = a[tid + (m << 10)];
    #pragma unroll
    for (int k = 2; k <= 32; k <<= 1) {
        #pragma unroll
        for (int j = k >> 1; j >= 1; j >>= 1) {
            #pragma unroll
            for (int m = 0; m < E; m++) {
                int t = tid + (m << 10);
                unsigned long long pv = __shfl_xor_sync(0xFFFFFFFFu, v[m], j);
                bool keepmax = (((t & k) == 0) == ((t & j) == 0));
                if (keepmax == (pv > v[m])) v[m] = pv;
            }
        }
    }
    #pragma unroll
    for (int m = 0; m < E; m++) a[tid + (m << 10)] = v[m];
    __syncthreads();
    for (int k = 64; k <= SZ; k <<= 1) {
        for (int j = k >> 1; j >= 32; j >>= 1) {
            #pragma unroll
            for (int m = 0; m < E; m++) {
                int t = tid + (m << 10);
                int ixj = t ^ j;
                if (ixj > t) {
                    unsigned long long u = a[t], w = a[ixj];
                    bool sw = ((t & k) == 0) ? (u < w) : (u > w);
                    if (sw) { a[t] = w; a[ixj] = u; }
                }
            }
            __syncthreads();
        }
        #pragma unroll
        for (int m = 0; m < E; m++) v[m] = a[tid + (m << 10)];
        #pragma unroll
        for (int j = 16; j >= 1; j >>= 1) {
            #pragma unroll
            for (int m = 0; m < E; m++) {
                int t = tid + (m << 10);
                unsigned long long pv = __shfl_xor_sync(0xFFFFFFFFu, v[m], j);
                bool keepmax = (((t & k) == 0) == ((t & j) == 0));
                if (keepmax == (pv > v[m])) v[m] = pv;
            }
        }
        #pragma unroll
        for (int m = 0; m < E; m++) a[tid + (m << 10)] = v[m];
        __syncthreads();
    }
}

// warp-aggregated candidate emit (up to 8 per thread)
template<int LVL, int CAPL, int LOFF>
__device__ __forceinline__ void emit8(int n, const unsigned* sbv, const int* rrv, int cnt) {
    int lane = threadIdx.x & 31;
    unsigned cinc = (unsigned)cnt;
    #pragma unroll
    for (int off = 1; off < 32; off <<= 1) {
        unsigned t = __shfl_up_sync(0xFFFFFFFFu, cinc, off);
        if (lane >= off) cinc += t;
    }
    unsigned total = __shfl_sync(0xFFFFFFFFu, cinc, 31);
    if (total == 0u) return;
    int b = n * 3 + LVL;
    unsigned base = 0;
    if (lane == 0) base = atomicAdd(&g_cnt[b], total);
    base = __shfl_sync(0xFFFFFFFFu, base, 0);
    unsigned pre = cinc - (unsigned)cnt;
    #pragma unroll
    for (int k = 0; k < 8; k++) {
        if (k >= cnt) break;
        unsigned slot = base + pre + (unsigned)k;
        if (slot < (unsigned)CAPL)
            g_cand[(size_t)n * CAPI + LOFF + slot] =
                ((unsigned long long)sbv[k] << 32) | (unsigned)(~rrv[k]);
    }
}

#define CAND_CHECK(px, cl, gc, m) do {                                       \
    if ((px) && ((gc) >= (m))) {                                             \
        float sc_ = sqrtf(sigm(cl) * sigm(gc));                              \
        sbv[cnt] = __float_as_uint(sc_); rrv[cnt] = rb + _k; cnt++;          \
    } _k++;                                                                  \
} while (0)

// core 8-px stencil evaluation from 3 row pointers (s0/s1/s2: row above/center/below at col x0)
#define STENCIL8_BODY(s0, s1, s2)                                            \
    float4 uA = *(const float4*)(s0), uB = *(const float4*)((s0) + 4);       \
    float4 cA = *(const float4*)(s1), cB = *(const float4*)((s1) + 4);       \
    float4 dA = *(const float4*)(s2), dB = *(const float4*)((s2) + 4);       \
    float cmL = hasL ? fmaxf(fmaxf((s0)[-1], (s1)[-1]), (s2)[-1]) : 0.f;     \
    float cmR = hasR ? fmaxf(fmaxf((s0)[8],  (s1)[8]),  (s2)[8])  : 0.f;     \
    float4 mA, mB;                                                           \
    mA.x = fmaxf(fmaxf(uA.x, cA.x), dA.x);                                   \
    mA.y = fmaxf(fmaxf(uA.y, cA.y), dA.y);                                   \
    mA.z = fmaxf(fmaxf(uA.z, cA.z), dA.z);                                   \
    mA.w = fmaxf(fmaxf(uA.w, cA.w), dA.w);                                   \
    mB.x = fmaxf(fmaxf(uB.x, cB.x), dB.x);                                   \
    mB.y = fmaxf(fmaxf(uB.y, cB.y), dB.y);                                   \
    mB.z = fmaxf(fmaxf(uB.z, cB.z), dB.z);                                   \
    mB.w = fmaxf(fmaxf(uB.w, cB.w), dB.w);                                   \
    float m0 = fmaxf(fmaxf(cmL,  mA.x), mA.y);                               \
    float m1 = fmaxf(fmaxf(mA.x, mA.y), mA.z);                               \
    float m2 = fmaxf(fmaxf(mA.y, mA.z), mA.w);                               \
    float m3 = fmaxf(fmaxf(mA.z, mA.w), mB.x);                               \
    float m4 = fmaxf(fmaxf(mA.w, mB.x), mB.y);                               \
    float m5 = fmaxf(fmaxf(mB.x, mB.y), mB.z);                               \
    float m6 = fmaxf(fmaxf(mB.y, mB.z), mB.w);                               \
    float m7 = fmaxf(fmaxf(mB.z, mB.w), cmR);                                \
    int _k = 0;                                                              \
    CAND_CHECK(p0, clA.x, cA.x, m0);                                         \
    CAND_CHECK(p1, clA.y, cA.y, m1);                                         \
    CAND_CHECK(p2, clA.z, cA.z, m2);                                         \
    CAND_CHECK(p3, clA.w, cA.w, m3);                                         \
    CAND_CHECK(p4, clB.x, cB.x, m4);                                         \
    CAND_CHECK(p5, clB.y, cB.y, m5);                                         \
    CAND_CHECK(p6, clB.z, cB.z, m6);                                         \
    CAND_CHECK(p7, clB.w, cB.w, m7);

// tiled score, 8 px/thread: block owns R rows of one (image,channel)
template<int H, int W, int R, int LVL, int CAPL, int LOFF>
__device__ __forceinline__ void score_tile8(const float* __restrict__ cls,
                                            const float* __restrict__ gau,
                                            float* sg, int bid) {
    constexpr int hw  = H * W;
    constexpr int RPC = H / R;
    constexpr int w4  = W / 4;
    constexpr int NF4 = (R + 2) * w4;
    int tid = threadIdx.x;
    int cb  = bid / RPC;
    int ry  = (bid - cb * RPC) * R;
    int n   = cb / CCH;
    size_t base = (size_t)cb * hw;

    for (int i = tid; i < NF4; i += 256) {
        int row = i / w4;
        int c4  = i - row * w4;
        int gy  = min(max(ry - 1 + row, 0), H - 1);
        ((float4*)sg)[i] = *(const float4*)(gau + base + (size_t)gy * W + c4 * 4);
    }
    __syncthreads();

    int t  = tid * 8;
    int lr = t / W;
    int x0 = t - lr * W;
    int y  = ry + lr;
    int sr = lr + 1;

    const float* cp = cls + base + (size_t)y * W + x0;
    float4 clA = *(const float4*)cp;
    float4 clB = *(const float4*)(cp + 4);
    bool iy = (y > 0) & (y < H - 1);
    bool hasL = x0 > 0, hasR = x0 < W - 8;
    bool p0 = iy && hasL && (clA.x > BOX_LOGIT_THRESH);
    bool p1 = iy && (clA.y > BOX_LOGIT_THRESH);
    bool p2 = iy && (clA.z > BOX_LOGIT_THRESH);
    bool p3 = iy && (clA.w > BOX_LOGIT_THRESH);
    bool p4 = iy && (clB.x > BOX_LOGIT_THRESH);
    bool p5 = iy && (clB.y > BOX_LOGIT_THRESH);
    bool p6 = iy && (clB.z > BOX_LOGIT_THRESH);
    bool p7 = iy && hasR && (clB.w > BOX_LOGIT_THRESH);

    unsigned sbv[8]; int rrv[8]; int cnt = 0;
    int rb = (cb - n * CCH) * hw + y * W + x0;

    if (p0 | p1 | p2 | p3 | p4 | p5 | p6 | p7) {
        const float* s0 = sg + (sr - 1) * W + x0;
        const float* s1 = sg + sr * W + x0;
        const float* s2 = sg + (sr + 1) * W + x0;
        STENCIL8_BODY(s0, s1, s2)
    }
    emit8<LVL, CAPL, LOFF>(n, sbv, rrv, cnt);
}

// untiled 8 px/thread (level 2)
template<int H, int W, int LVL, int CAPL, int LOFF>
__device__ __forceinline__ void score_body8(const float* __restrict__ cls,
                                            const float* __restrict__ gau, int bid) {
    constexpr int hw  = H * W;
    constexpr int CHW = CCH * hw;
    constexpr int OPI = CHW / 8;
    int q   = bid * 256 + threadIdx.x;
    int n   = q / OPI;
    int pix = q * 8;
    int r   = pix - n * CHW;
    int pp  = r % hw;
    int y   = pp / W;
    int x0  = pp & (W - 1);

    const float* cp = cls + (size_t)pix;
    float4 clA = *(const float4*)cp;
    float4 clB = *(const float4*)(cp + 4);
    bool iy = (y > 0) & (y < H - 1);
    bool hasL = x0 > 0, hasR = x0 < W - 8;
    bool p0 = iy && hasL && (clA.x > BOX_LOGIT_THRESH);
    bool p1 = iy && (clA.y > BOX_LOGIT_THRESH);
    bool p2 = iy && (clA.z > BOX_LOGIT_THRESH);
    bool p3 = iy && (clA.w > BOX_LOGIT_THRESH);
    bool p4 = iy && (clB.x > BOX_LOGIT_THRESH);
    bool p5 = iy && (clB.y > BOX_LOGIT_THRESH);
    bool p6 = iy && (clB.z > BOX_LOGIT_THRESH);
    bool p7 = iy && hasR && (clB.w > BOX_LOGIT_THRESH);

    unsigned sbv[8]; int rrv[8]; int cnt = 0;
    int rb = r;

    if (p0 | p1 | p2 | p3 | p4 | p5 | p6 | p7) {
        const float* Gb = gau + (size_t)(pix - pp);
        const float* s0 = Gb + pp - W;
        const float* s1 = Gb + pp;
        const float* s2 = Gb + pp + W;
        STENCIL8_BODY(s0, s1, s2)
    }
    emit8<LVL, CAPL, LOFF>(n, sbv, rrv, cnt);
}

__global__ void __launch_bounds__(256) k_score_all(
    const float* __restrict__ c0, const float* __restrict__ g0,
    const float* __restrict__ c1, const float* __restrict__ g1,
    const float* __restrict__ c2, const float* __restrict__ g2) {
    __shared__ __align__(16) float sg[10 * 256];   // lvl0: 10x256, lvl1: 18x128
    int bid = blockIdx.x;
    if (bid < 6400)       score_tile8<160,256,8, 0,CAP0,0>   (c0, g0, sg, bid);
    else if (bid < 8000)  score_tile8<80, 128,16,1,CAP1,CAP0>(c1, g1, sg, bid - 6400);
    else                  score_body8<40, 64, 2,CAP2,CAP0+CAP1>(c2, g2, bid - 8000);
}

// top-500 select per (image, level): smem 2-pass histogram + hybrid sort + fused solve
__global__ void __launch_bounds__(1024) k_select(const float* __restrict__ g0,
                                                 const float* __restrict__ g1,
                                                 const float* __restrict__ g2) {
    int b = blockIdx.x;
    int n = b / 3, lvl = b % 3;
    __shared__ unsigned int sh_c[1024];
    __shared__ unsigned int sh_f[256];
    __shared__ unsigned long long sel[4096];
    __shared__ unsigned int sT, sM, sAbove;
    __shared__ int sB;
    int tid = threadIdx.x;

    unsigned cnt = min(g_cnt[b], (unsigned)c_cap[lvl]);
    const unsigned long long* cand = &g_cand[(size_t)n * CAPI + c_loff[lvl]];
    const ulonglong2* cand2 = (const ulonglong2*)cand;
    unsigned half = cnt >> 1;
    bool odd = (cnt & 1u) != 0u;

    sh_c[tid] = 0;
    if (tid == 0) { sM = 0; sB = -1; sAbove = 0; sT = 0; }
    __syncthreads();
    if (tid == 0) g_cnt[b] = 0;   // safe: all threads read cnt before the barrier

    // pass 1: coarse hist on sb>>20 (vectorized)
    for (unsigned i = tid; i < half; i += 1024) {
        ulonglong2 kk = cand2[i];
        atomicAdd(&sh_c[(unsigned)(kk.x >> 32) >> 20], 1u);
        atomicAdd(&sh_c[(unsigned)(kk.y >> 32) >> 20], 1u);
    }
    if (tid == 0 && odd) atomicAdd(&sh_c[(unsigned)(cand[cnt - 1] >> 32) >> 20], 1u);
    __syncthreads();

    for (int off = 1; off < 1024; off <<= 1) {
        unsigned v = sh_c[tid];
        if (tid + off < 1024) v += sh_c[tid + off];
        __syncthreads();
        sh_c[tid] = v;
        __syncthreads();
    }
    if (sh_c[tid] >= TOPN && (tid == 1023 || sh_c[tid + 1] < TOPN)) {
        sB = tid;
        sAbove = (tid == 1023) ? 0u : sh_c[tid + 1];
    }
    if (tid < 256) sh_f[tid] = 0;
    __syncthreads();
    int B = sB;
    unsigned above = sAbove;

    // pass 2: fine hist within coarse bin B on (sb>>12)&255
    if (B >= 0) {
        for (unsigned i = tid; i < half; i += 1024) {
            ulonglong2 kk = cand2[i];
            unsigned hx = (unsigned)(kk.x >> 32), hy = (unsigned)(kk.y >> 32);
            if ((int)(hx >> 20) == B) atomicAdd(&sh_f[(hx >> 12) & 255], 1u);
            if ((int)(hy >> 20) == B) atomicAdd(&sh_f[(hy >> 12) & 255], 1u);
        }
        if (tid == 0 && odd) {
            unsigned hz = (unsigned)(cand[cnt - 1] >> 32);
            if ((int)(hz >> 20) == B) atomicAdd(&sh_f[(hz >> 12) & 255], 1u);
        }
    }
    __syncthreads();
    for (int off = 1; off < 256; off <<= 1) {
        unsigned v = 0;
        if (tid < 256) { v = sh_f[tid]; if (tid + off < 256) v += sh_f[tid + off]; }
        __syncthreads();
        if (tid < 256) sh_f[tid] = v;
        __syncthreads();
    }
    if (B >= 0 && tid < 256) {
        unsigned cum = above + sh_f[tid];
        unsigned nxt = (tid == 255) ? above : above + sh_f[tid + 1];
        if (cum >= TOPN && nxt < TOPN) sT = ((unsigned)B << 8) | (unsigned)tid;
    }
    __syncthreads();
    unsigned T = sT;

    // pass 3: collect keys >= T (vectorized), sort, emit top-500
    for (unsigned i = tid; i < half; i += 1024) {
        ulonglong2 kk = cand2[i];
        if ((unsigned)(kk.x >> 44) >= T) {
            unsigned p = atomicAdd(&sM, 1u);
            if (p < 4096) sel[p] = kk.x;
        }
        if ((unsigned)(kk.y >> 44) >= T) {
            unsigned p = atomicAdd(&sM, 1u);
            if (p < 4096) sel[p] = kk.y;
        }
    }
    if (tid == 0 && odd) {
        unsigned long long kz = cand[cnt - 1];
        if ((unsigned)(kz >> 44) >= T) {
            unsigned p = atomicAdd(&sM, 1u);
            if (p < 4096) sel[p] = kz;
        }
    }
    __syncthreads();
    unsigned mM = min(sM, 4096u);
    for (int i = tid; i < 4096; i += 1024)
        if ((unsigned)i >= mM) sel[i] = 0ull;
    __syncthreads();
    bitonic_desc_h<4096>(sel);

    if (tid < TOPN) {
        int t = n * NCAND + lvl * TOPN + tid;
        unsigned long long key = sel[tid];
        g_top[t] = key;

        int H, W, step; const float* G;
        if (lvl == 0)      { H = 160; W = 256; step = 8;  G = g0; }
        else if (lvl == 1) { H = 80;  W = 128; step = 16; G = g1; }
        else               { H = 40;  W = 64;  step = 32; G = g2; }
        float sc = __uint_as_float((unsigned)(key >> 32));
        unsigned flat = ~(unsigned)key;
        int hw = H * W;
        if (!(sc > 0.f) || flat >= (unsigned)(CCH * hw)) {
            g_x1[t]=0.f; g_y1[t]=0.f; g_x2[t]=0.f; g_y2[t]=0.f; g_lb[t]=1; g_vd[t]=0;
        } else {
            int c = (int)(flat / hw);
            int rem = (int)(flat - (unsigned)c * hw);
            int y = rem / W, x = rem - y * W;
            const float* Bp = G + ((size_t)(n * CCH + c)) * hw;
            auto LV = [&](int yy, int xx) -> float {
                yy = min(max(yy, 0), H - 1);
                xx = min(max(xx, 0), W - 1);
                return log1pf(expf(-Bp[yy * W + xx])) * 0.125f;
            };
            float l0 = LV(y, x);
            float lxp = LV(y, x+1), lxm = LV(y, x-1);
            float lyp = LV(y+1, x), lym = LV(y-1, x);
            float Ax = (lxp + lxm - 2.f * l0) * 0.5f;
            float Ay = (lyp + lym - 2.f * l0) * 0.5f;
            bool px = Ax > 1e-8f, py = Ay > 1e-8f;
            float Axs = px ? Ax : 1.f, Ays = py ? Ay : 1.f;
            float mux = (float)x - (lxp - lxm) / (4.f * Axs);
            float muy = (float)y - (lyp - lym) / (4.f * Ays);
            float wb = (px ? rsqrtf(2.f * Axs) : 0.f) * (float)step;
            float hb = (py ? rsqrtf(2.f * Ays) : 0.f) * (float)step;
            float x1 = mux * (float)step - 0.5f * wb + (float)(step - 1) * 0.5f;
            float y1 = muy * (float)step - 0.5f * hb + (float)(step - 1) * 0.5f;
            bool vd = (wb > 0.f) && (hb > 0.f);
            float x2 = x1 + wb - 1.f, y2 = y1 + hb - 1.f;
            g_x1[t] = fminf(fmaxf(x1, 0.f), 2047.f);
            g_x2[t] = fminf(fmaxf(x2, 0.f), 2047.f);
            g_y1[t] = fminf(fmaxf(y1, 0.f), 1279.f);
            g_y2[t] = fminf(fmaxf(y2, 0.f), 1279.f);
            g_lb[t] = c + 1; g_vd[t] = vd ? 1 : 0;
        }
    }
}

// per-image NMS: hybrid sort, then exact per-class greedy (one warp per class)
__global__ void __launch_bounds__(1024) k_nms(float* __restrict__ out) {
    __shared__ unsigned long long skey[2048];
    __shared__ float bx1[NCAND], by1[NCAND], bx2[NCAND], by2[NCAND];
    __shared__ short slb[NCAND];
    __shared__ unsigned char keep[NCAND];
    __shared__ short cls_list[NCAND];
    __shared__ int   ofs[82];
    __shared__ int   s_ti[100];
    int n = blockIdx.x, tid = threadIdx.x;
    int w = tid >> 5, lane = tid & 31;

    for (int p = tid; p < 2048; p += 1024) {
        unsigned long long kk = 0ull;
        if (p < NCAND) {
            int gi = n * NCAND + p;
            float sc = __uint_as_float((unsigned)(g_top[gi] >> 32));
            float sv = g_vd[gi] ? sc : -1.f;
            unsigned bits = __float_as_uint(sv);
            unsigned ord = (bits & 0x80000000u) ? ~bits : (bits | 0x80000000u);
            kk = ((unsigned long long)ord << 32) | (0xFFFFFFFFu - (unsigned)p);
        }
        skey[p] = kk;
    }
    __syncthreads();
    bitonic_desc_h<2048>(skey);

    for (int p = tid; p < NCAND; p += 1024) {
        int pos = (int)(0xFFFFFFFFu - (unsigned)skey[p]);
        int gi = n * NCAND + pos;
        bx1[p]=g_x1[gi]; by1[p]=g_y1[gi]; bx2[p]=g_x2[gi]; by2[p]=g_y2[gi];
        slb[p]=(short)g_lb[gi]; keep[p]=g_vd[gi];
    }
    if (tid < 82) ofs[tid] = 0;
    __syncthreads();

    for (int p = tid; p < NCAND; p += 1024)
        if (keep[p]) atomicAdd((unsigned*)&ofs[slb[p]], 1u);
    __syncthreads();
    if (tid == 0) {
        int acc = 0;
        for (int c = 1; c <= 80; c++) { int v = ofs[c]; ofs[c] = acc; acc += v; }
        ofs[81] = acc;
        ofs[0]  = 0;
    }
    __syncthreads();

    for (int lbl = w + 1; lbl <= 80; lbl += 32) {
        int start = ofs[lbl];
        int fill = 0;
        for (int base = 0; base < NCAND; base += 32) {
            int p = base + lane;
            bool match = (p < NCAND) && keep[p] && (slb[p] == (short)lbl);
            unsigned bal = __ballot_sync(0xFFFFFFFFu, match);
            if (match) {
                int pre = __popc(bal & ((1u << lane) - 1u));
                cls_list[start + fill + pre] = (short)p;
            }
            fill += __popc(bal);
        }
    }
    __syncthreads();

    for (int lbl = w + 1; lbl <= 80; lbl += 32) {
        int start = ofs[lbl];
        int k = ofs[lbl + 1] - start;
        if (k < 2) continue;
        for (int t0 = 0; t0 < k; t0 += 32) {
            int e = t0 + lane;
            bool in = e < k;
            int idx = in ? (int)cls_list[start + e] : 0;
            float x1 = 0, y1 = 0, x2 = 0, y2 = 0, ar = 1.f;
            bool alive = false;
            if (in) {
                x1 = bx1[idx]; y1 = by1[idx]; x2 = bx2[idx]; y2 = by2[idx];
                ar = (x2 - x1 + 1.f) * (y2 - y1 + 1.f);
                alive = keep[idx] != 0;
            }
            if (alive) {
                for (int qe = 0; qe < t0; qe++) {
                    int qi = (int)cls_list[start + qe];
                    if (!keep[qi]) continue;
                    float qx1 = bx1[qi], qy1 = by1[qi], qx2 = bx2[qi], qy2 = by2[qi];
                    float iw = fmaxf(fminf(x2, qx2) - fmaxf(x1, qx1) + 1.f, 0.f);
                    float ih = fmaxf(fminf(y2, qy2) - fmaxf(y1, qy1) + 1.f, 0.f);
                    float inter = iw * ih;
                    float qar = (qx2 - qx1 + 1.f) * (qy2 - qy1 + 1.f);
                    if (inter / (ar + qar - inter + 1e-9f) > 0.5f) { alive = false; break; }
                }
            }
            int lim = min(32, k - t0);
            unsigned sup = 0;
            for (int m = 0; m < lim - 1; m++) {
                float mx1 = __shfl_sync(0xFFFFFFFFu, x1, m);
                float my1 = __shfl_sync(0xFFFFFFFFu, y1, m);
                float mx2 = __shfl_sync(0xFFFFFFFFu, x2, m);
                float my2 = __shfl_sync(0xFFFFFFFFu, y2, m);
                float mar = __shfl_sync(0xFFFFFFFFu, ar, m);
                if (in && m < lane) {
                    float iw = fmaxf(fminf(x2, mx2) - fmaxf(x1, mx1) + 1.f, 0.f);
                    float ih = fmaxf(fminf(y2, my2) - fmaxf(y1, my1) + 1.f, 0.f);
                    float inter = iw * ih;
                    if (inter / (ar + mar - inter + 1e-9f) > 0.5f) sup |= (1u << m);
                }
            }
            for (int m = 0; m < lim - 1; m++) {
                unsigned bal = __ballot_sync(0xFFFFFFFFu, alive);
                if (lane > m && ((bal >> m) & 1u) && ((sup >> m) & 1u)) alive = false;
            }
            if (in) keep[idx] = alive ? 1 : 0;
        }
    }
    __syncthreads();

    if (tid < 32) {
        int cnt = 0;
        for (int pass = 0; pass < 2; pass++) {
            for (int b2 = 0; b2 < NCAND && cnt < 100; b2 += 32) {
                int i2 = b2 + lane;
                bool pr = (i2 < NCAND) && ((pass == 0) ? (keep[i2] != 0) : (keep[i2] == 0));
                unsigned ww = __ballot_sync(0xFFFFFFFFu, pr);
                int pre = __popc(ww & ((1u << lane) - 1u));
                if (pr && cnt + pre < 100) s_ti[cnt + pre] = i2;
                cnt += __popc(ww);
            }
            if (cnt > 100) cnt = 100;
        }
    }
    __syncthreads();

    if (tid < 100) {
        int p = s_ti[tid];
        unsigned ord = (unsigned)(skey[p] >> 32);
        float s = (ord & 0x80000000u) ? __uint_as_float(ord ^ 0x80000000u)
                                      : __uint_as_float(~ord);
        float tv = keep[p] ? s : -1.f;
        out[n*400 + tid*4 + 0] = bx1[p];
        out[n*400 + tid*4 + 1] = by1[p];
        out[n*400 + tid*4 + 2] = bx2[p];
        out[n*400 + tid*4 + 3] = by2[p];
        out[1600 + n*100 + tid] = tv;
        out[2000 + n*100 + tid] = (float)slb[p];
        out[2400 + n*100 + tid] = (tv > 0.f) ? 1.f : 0.f;
    }
}

extern "C" void kernel_launch(void* const* d_in, const int* in_sizes, int n_in,
                              void* d_out, int out_size) {
    const float *cls[3], *gau[3];
    if (in_sizes[0] == in_sizes[1]) {          // interleaved
        cls[0]=(const float*)d_in[0]; gau[0]=(const float*)d_in[1];
        cls[1]=(const float*)d_in[2]; gau[1]=(const float*)d_in[3];
        cls[2]=(const float*)d_in[4]; gau[2]=(const float*)d_in[5];
    } else {                                   // grouped
        cls[0]=(const float*)d_in[0]; cls[1]=(const float*)d_in[1]; cls[2]=(const float*)d_in[2];
        gau[0]=(const float*)d_in[3]; gau[1]=(const float*)d_in[4]; gau[2]=(const float*)d_in[5];
    }
    float* out = (float*)d_out;

    k_score_all<<<8400, 256>>>(cls[0], gau[0], cls[1], gau[1], cls[2], gau[2]);
    k_select<<<NIMG * 3, 1024>>>(gau[0], gau[1], gau[2]);
    k_nms<<<NIMG, 1024>>>(out);
}